// round 9
// baseline (speedup 1.0000x reference)
#include <cuda_runtime.h>
#include <math.h>
#include <stdint.h>

#define Bn   32
#define Sn   1024
#define Dn   512
#define Hn   8
#define Ln   4
#define BSn  (Bn*Sn)

// ------------------------- scratch (device globals) -------------------------
__device__ float    g_x[(size_t)BSn * Dn];
__device__ uint32_t g_xpk[(size_t)BSn * 256];
__device__ uint32_t g_qpk[(size_t)256 * 1024 * 32];
__device__ uint32_t g_kpk[(size_t)256 * 1024 * 32];
__device__ float    g_vtmp[(size_t)256 * 1024 * 64];
__device__ uint32_t g_vpk[(size_t)256 * 512 * 64];
__device__ uint32_t g_ctxpk[(size_t)BSn * 256];
__device__ float    g_t1[(size_t)BSn * Dn];
__device__ uint32_t g_t2pk[(size_t)BSn * 256];
__device__ uint32_t g_wqkv[(size_t)Ln * 1536 * 256];   // [L][N][Kp] transposed
__device__ uint32_t g_wo[(size_t)Ln * 512 * 256];
__device__ uint32_t g_w1[(size_t)Ln * 512 * 256];
__device__ uint32_t g_w2[(size_t)Ln * 512 * 256];
__device__ float    g_logits[BSn];

// pack two fp32 into bf16x2: low half = first arg (even k), high = second
__device__ __forceinline__ uint32_t pk2(float lo, float hi) {
    uint32_t r;
    asm("cvt.rn.bf16x2.f32 %0, %1, %2;" : "=r"(r) : "f"(hi), "f"(lo));
    return r;
}

__device__ __forceinline__ void cpa16(uint32_t dst, const void* src) {
    asm volatile("cp.async.cg.shared.global [%0], [%1], 16;" :: "r"(dst), "l"(src));
}
#define CP_COMMIT() asm volatile("cp.async.commit_group;")
#define CP_WAIT(N)  asm volatile("cp.async.wait_group %0;" :: "n"(N))

#define MMA_BF16(C0,C1,C2,C3,A0,A1,A2,A3,B0,B1)                              \
    asm volatile(                                                            \
        "mma.sync.aligned.m16n8k16.row.col.f32.bf16.bf16.f32 "               \
        "{%0,%1,%2,%3}, {%4,%5,%6,%7}, {%8,%9}, {%0,%1,%2,%3};"              \
        : "+f"(C0), "+f"(C1), "+f"(C2), "+f"(C3)                             \
        : "r"(A0), "r"(A1), "r"(A2), "r"(A3), "r"(B0), "r"(B1))

__device__ __forceinline__ void ldm4(unsigned& r0, unsigned& r1,
                                     unsigned& r2, unsigned& r3, uint32_t a) {
    asm volatile("ldmatrix.sync.aligned.m8n8.x4.shared.b16 {%0,%1,%2,%3}, [%4];"
                 : "=r"(r0), "=r"(r1), "=r"(r2), "=r"(r3) : "r"(a));
}

// ============================ weight pack (tiled transpose) =================
// src fp32 [L][2*KpL][N] -> dst bf16x2 [L][N][KpL]
__global__ void pack_w_kernel(const float* __restrict__ src,
                              uint32_t* __restrict__ dst, int KpL, int N) {
    __shared__ uint32_t t[32][33];
    int layer = blockIdx.z;
    int kp0 = blockIdx.x * 32;
    int n0  = blockIdx.y * 32;
    const float* s = src + (size_t)layer * 2 * KpL * N;
    uint32_t* d = dst + (size_t)layer * N * KpL;
    int ty = threadIdx.x >> 5, tx = threadIdx.x & 31;
    for (int r = ty; r < 32; r += 8) {
        int kp = kp0 + r;
        t[r][tx] = pk2(s[(size_t)(2 * kp) * N + n0 + tx],
                       s[(size_t)(2 * kp + 1) * N + n0 + tx]);
    }
    __syncthreads();
    for (int r = ty; r < 32; r += 8)
        d[(size_t)(n0 + r) * KpL + kp0 + tx] = t[tx][r];
}

// ============================ embed =========================================
__global__ void embed_kernel(const float* __restrict__ loc,
                             const float* __restrict__ tdist,
                             const float* __restrict__ Wtd,
                             const float* __restrict__ btd,
                             const float* __restrict__ Wemb,
                             const float* __restrict__ bemb,
                             float* __restrict__ x,
                             uint32_t* __restrict__ xpk) {
    int tok = blockIdx.x;
    const float* lp = loc + (size_t)tok * 16;
    const float* tp = tdist + (size_t)tok * 8;
    float in[19];
#pragma unroll
    for (int i = 0; i < 16; i++) in[i] = lp[i];
#pragma unroll
    for (int j = 0; j < 3; j++) {
        float s = btd[j];
#pragma unroll
        for (int i = 0; i < 8; i++) s += tp[i] * Wtd[i * 3 + j];
        in[16 + j] = s;
    }
    int d = threadIdx.x * 4;
    float4 acc = *(const float4*)(bemb + d);
#pragma unroll
    for (int i = 0; i < 19; i++) {
        float4 w = *(const float4*)(Wemb + i * 512 + d);
        float s = in[i];
        acc.x += s * w.x; acc.y += s * w.y; acc.z += s * w.z; acc.w += s * w.w;
    }
    *(float4*)(x + (size_t)tok * 512 + d) = acc;
    uint2 p;
    p.x = pk2(acc.x, acc.y);
    p.y = pk2(acc.z, acc.w);
    *(uint2*)(xpk + (size_t)tok * 256 + threadIdx.x * 2) = p;
}

// ============================ bf16 tensor-core GEMM (ldmatrix) ==============
// A packed [M][Kp], W packed [N][Kp] (both k-pair bf16x2).
// Block 128x128, chunk 8 kpairs (k16), 8 warps 2x4, warp tile 64x32.
template <int MODE>
__global__ __launch_bounds__(256)
void bf16_gemm(const uint32_t* __restrict__ Apk, const uint32_t* __restrict__ Wpk,
               const float* __restrict__ bias,
               float* __restrict__ Cf, uint32_t* __restrict__ Cpk,
               uint32_t* __restrict__ Qpk, uint32_t* __restrict__ Kpk,
               float* __restrict__ Vtmp,
               int M, int N, int Kp) {
    __shared__ uint32_t As[2][128 * 12];   // [m][kpair] pitch 12
    __shared__ uint32_t Ws[2][128 * 12];   // [n][kpair] pitch 12

    const int tid  = threadIdx.x;
    const int warp = tid >> 5;
    const int lane = tid & 31;
    const int wm = warp >> 2;
    const int wn = warp & 3;
    const int qid = lane >> 2;
    const int tq  = lane & 3;
    const int l7  = lane & 7;
    const int g   = lane >> 3;

    const int bm = blockIdx.y * 128;
    const int bn = blockIdx.x * 128;

    const int lrow = tid >> 1;             // 0..127
    const int lkp  = (tid & 1) << 2;       // 0 or 4

    const uint32_t* Ag = Apk + (size_t)(bm + lrow) * Kp + lkp;
    const uint32_t* Wg = Wpk + (size_t)(bn + lrow) * Kp + lkp;

    uint32_t aAd[2], aWd[2];
    {
        uint32_t a0 = (uint32_t)__cvta_generic_to_shared(&As[0][0]);
        uint32_t a1 = (uint32_t)__cvta_generic_to_shared(&As[1][0]);
        uint32_t w0 = (uint32_t)__cvta_generic_to_shared(&Ws[0][0]);
        uint32_t w1 = (uint32_t)__cvta_generic_to_shared(&Ws[1][0]);
        aAd[0] = a0 + (lrow * 12 + lkp) * 4;
        aAd[1] = a1 + (lrow * 12 + lkp) * 4;
        aWd[0] = w0 + (lrow * 12 + lkp) * 4;
        aWd[1] = w1 + (lrow * 12 + lkp) * 4;
    }

    // fragment-load addresses (ldmatrix)
    //  A-frag: row = wm*64 + am*16 + l7 + (g&1)*8, col = (g>>1)*4
    //  B-frag: row = wn*32 + anp*16 + l7 + (g>>1)*8, col = (g&1)*4
    const int arow = wm * 64 + l7 + (g & 1) * 8;
    const int acol = (g >> 1) * 4;
    const int brow = wn * 32 + l7 + ((g >> 1) & 1) * 8;
    const int bcol = (g & 1) * 4;
    uint32_t aFr[2], wFr[2];
    {
        uint32_t a0 = (uint32_t)__cvta_generic_to_shared(&As[0][0]);
        uint32_t a1 = (uint32_t)__cvta_generic_to_shared(&As[1][0]);
        uint32_t w0 = (uint32_t)__cvta_generic_to_shared(&Ws[0][0]);
        uint32_t w1 = (uint32_t)__cvta_generic_to_shared(&Ws[1][0]);
        aFr[0] = a0 + (arow * 12 + acol) * 4;
        aFr[1] = a1 + (arow * 12 + acol) * 4;
        wFr[0] = w0 + (brow * 12 + bcol) * 4;
        wFr[1] = w1 + (brow * 12 + bcol) * 4;
    }

    // prologue: chunk 0
    cpa16(aAd[0], Ag);
    cpa16(aWd[0], Wg);
    CP_COMMIT();

    float acc[4][4][4];
#pragma unroll
    for (int i = 0; i < 4; i++)
#pragma unroll
        for (int j = 0; j < 4; j++)
#pragma unroll
            for (int c = 0; c < 4; c++) acc[i][j][c] = 0.f;

    const int nck = Kp >> 3;
    for (int kc = 0; kc < nck; kc++) {
        const int s = kc & 1;
        if (kc + 1 < nck) {
            cpa16(aAd[s ^ 1], Ag + (kc + 1) * 8);
            cpa16(aWd[s ^ 1], Wg + (kc + 1) * 8);
            CP_COMMIT();
            CP_WAIT(1);
        } else {
            CP_WAIT(0);
        }
        __syncthreads();

        unsigned a[4][4], b[4][2];
#pragma unroll
        for (int am = 0; am < 4; am++)
            ldm4(a[am][0], a[am][1], a[am][2], a[am][3],
                 aFr[s] + am * 16 * 12 * 4);
#pragma unroll
        for (int anp = 0; anp < 2; anp++)
            ldm4(b[2 * anp][0], b[2 * anp][1], b[2 * anp + 1][0], b[2 * anp + 1][1],
                 wFr[s] + anp * 16 * 12 * 4);
#pragma unroll
        for (int am = 0; am < 4; am++)
#pragma unroll
            for (int an = 0; an < 4; an++)
                MMA_BF16(acc[am][an][0], acc[am][an][1],
                         acc[am][an][2], acc[am][an][3],
                         a[am][0], a[am][1], a[am][2], a[am][3],
                         b[an][0], b[an][1]);
        __syncthreads();
    }

    // epilogue
#pragma unroll
    for (int am = 0; am < 4; am++) {
        int r0 = bm + wm * 64 + am * 16 + qid;
#pragma unroll
        for (int an = 0; an < 4; an++) {
            int col = bn + wn * 32 + an * 8 + 2 * tq;
            float b0 = bias[col], b1 = bias[col + 1];
            float v0 = acc[am][an][0] + b0;
            float v1 = acc[am][an][1] + b1;
            float v2 = acc[am][an][2] + b0;
            float v3 = acc[am][an][3] + b1;
            if (MODE == 0) {
                *(float2*)(Cf + (size_t)r0 * N + col)       = make_float2(v0, v1);
                *(float2*)(Cf + (size_t)(r0 + 8) * N + col) = make_float2(v2, v3);
            } else if (MODE == 1) {
                v0 = fmaxf(v0, 0.f); v1 = fmaxf(v1, 0.f);
                v2 = fmaxf(v2, 0.f); v3 = fmaxf(v3, 0.f);
                Cpk[(size_t)r0 * (N >> 1) + (col >> 1)]       = pk2(v0, v1);
                Cpk[(size_t)(r0 + 8) * (N >> 1) + (col >> 1)] = pk2(v2, v3);
            } else {
                int bb = r0 >> 10;
                int sr = r0 & 1023;
                int h  = (col >> 6) & 7;
                size_t bh = (size_t)(bb * 8 + h);
                if (col < 512) {
                    v0 *= 0.125f; v1 *= 0.125f; v2 *= 0.125f; v3 *= 0.125f;
                    size_t base = (bh * 1024 + sr) * 32 + ((col & 63) >> 1);
                    Qpk[base]            = pk2(v0, v1);
                    Qpk[base + 8 * 32]   = pk2(v2, v3);
                } else if (col < 1024) {
                    size_t base = (bh * 1024 + sr) * 32 + ((col & 63) >> 1);
                    Kpk[base]            = pk2(v0, v1);
                    Kpk[base + 8 * 32]   = pk2(v2, v3);
                } else {
                    size_t base = (bh * 1024 + sr) * 64 + (col & 63);
                    *(float2*)(Vtmp + base)            = make_float2(v0, v1);
                    *(float2*)(Vtmp + base + 8 * 64)   = make_float2(v2, v3);
                }
            }
        }
    }
}

// ============================ V repack (key-pair packing) ===================
__global__ __launch_bounds__(256)
void repack_v_kernel(const float* __restrict__ Vtmp, uint32_t* __restrict__ Vpk) {
    int bh  = blockIdx.x >> 3;
    int kp0 = (blockIdx.x & 7) * 64;
    const float* src = Vtmp + (size_t)bh * 1024 * 64;
    uint32_t* dst = Vpk + ((size_t)bh * 512 + kp0) * 64;
    for (int i = threadIdx.x; i < 64 * 64; i += 256) {
        int kpl = i >> 6;
        int d   = i & 63;
        int key0 = 2 * (kp0 + kpl);
        dst[(size_t)kpl * 64 + d] = pk2(src[(size_t)key0 * 64 + d],
                                        src[(size_t)(key0 + 1) * 64 + d]);
    }
}

// ============================ flash attention (bf16 + ldmatrix) =============
#define QP  36
#define KPT 36
#define VPT 72
#define KTILE (64 * KPT)
#define VTILE (32 * VPT)
#define FSTG (KTILE + VTILE)
#define QTILE (128 * QP)
#define FLASH_SMEM ((2 * FSTG + QTILE) * 4)

__global__ __launch_bounds__(256)
void flash_bf16_kernel(const uint32_t* __restrict__ Qpk,
                       const uint32_t* __restrict__ Kpk,
                       const uint32_t* __restrict__ Vpk,
                       uint32_t* __restrict__ ctxpk,
                       const int* __restrict__ dlen) {
    extern __shared__ uint32_t smu[];

    const int qt = blockIdx.x;
    const int bh = blockIdx.y;
    const int b  = bh >> 3;
    const int len = dlen[b];
    const int nk = (len + 63) >> 6;

    const int tid = threadIdx.x;
    const int warp = tid >> 5;
    const int lane = tid & 31;
    const int qid = lane >> 2;
    const int tq  = lane & 3;
    const int l7  = lane & 7;
    const int g   = lane >> 3;
    const int m0  = warp * 16;

    const uint32_t* Qg = Qpk + ((size_t)bh * 1024 + qt * 128) * 32;
    const uint32_t* Kg = Kpk + (size_t)bh * 1024 * 32;
    const uint32_t* Vg = Vpk + (size_t)bh * 512 * 64;

    uint32_t* Qs = smu + 2 * FSTG;
    uint32_t smbase = (uint32_t)__cvta_generic_to_shared(smu);
    uint32_t qbase  = smbase + 2 * FSTG * 4;

    // fragment addresses
    //  A-style (Q/P): row = m0 + l7 + (g&1)*8, col = s*8 + (g>>1)*4
    //  B-style (K):   row = np*16 + l7 + (g>>1)*8, col = s*8 + (g&1)*4
    const int aRow = m0 + l7 + (g & 1) * 8;
    const int aCol = (g >> 1) * 4;
    const uint32_t aFrag = qbase + (aRow * QP + aCol) * 4;
    const int kRow = l7 + ((g >> 1) & 1) * 8;
    const int kCol = (g & 1) * 4;

    // group 1: Q tile
#pragma unroll
    for (int u = 0; u < 4; u++) {
        int f = tid + u * 256;
        int r = f >> 3, c4 = (f & 7) << 2;
        cpa16(qbase + (r * QP + c4) * 4, Qg + (size_t)r * 32 + c4);
    }
    CP_COMMIT();
    // group 2: K/V tile 0
    {
        uint32_t kd = smbase, vd = smbase + KTILE * 4;
#pragma unroll
        for (int u = 0; u < 2; u++) {
            int f = tid + u * 256;
            int rk = f >> 3, ck = (f & 7) << 2;
            cpa16(kd + (rk * KPT + ck) * 4, Kg + (size_t)rk * 32 + ck);
            int rv = f >> 4, cv = (f & 15) << 2;
            cpa16(vd + (rv * VPT + cv) * 4, Vg + (size_t)rv * 64 + cv);
        }
        CP_COMMIT();
    }
    CP_WAIT(1);
    __syncthreads();

    // Q fragments via ldmatrix
    unsigned aq[4][4];
#pragma unroll
    for (int s = 0; s < 4; s++)
        ldm4(aq[s][0], aq[s][1], aq[s][2], aq[s][3], aFrag + s * 8 * 4);

    float mr0 = -1e30f, mr1 = -1e30f, lr0 = 0.f, lr1 = 0.f;
    float O[8][4];
#pragma unroll
    for (int n = 0; n < 8; n++)
#pragma unroll
        for (int c = 0; c < 4; c++) O[n][c] = 0.f;

    uint32_t* Pw = Qs + m0 * QP;

    for (int kt = 0; kt < nk; kt++) {
        __syncthreads();
        if (kt + 1 < nk) {
            uint32_t sb = smbase + ((kt + 1) & 1) * FSTG * 4;
            uint32_t kd = sb, vd = sb + KTILE * 4;
            const uint32_t* kg = Kg + (size_t)(kt + 1) * 64 * 32;
            const uint32_t* vg = Vg + (size_t)(kt + 1) * 32 * 64;
#pragma unroll
            for (int u = 0; u < 2; u++) {
                int f = tid + u * 256;
                int rk = f >> 3, ck = (f & 7) << 2;
                cpa16(kd + (rk * KPT + ck) * 4, kg + (size_t)rk * 32 + ck);
                int rv = f >> 4, cv = (f & 15) << 2;
                cpa16(vd + (rv * VPT + cv) * 4, vg + (size_t)rv * 64 + cv);
            }
            CP_COMMIT();
            CP_WAIT(1);
        } else {
            CP_WAIT(0);
        }
        __syncthreads();

        const uint32_t ksBase = smbase + (kt & 1) * FSTG * 4;
        const uint32_t* Vs = smu + (kt & 1) * FSTG + KTILE;

        // ---- S = Q @ K^T ----
        float c[8][4];
#pragma unroll
        for (int n = 0; n < 8; n++)
#pragma unroll
            for (int j = 0; j < 4; j++) c[n][j] = 0.f;

#pragma unroll
        for (int s = 0; s < 4; s++) {
#pragma unroll
            for (int np = 0; np < 4; np++) {
                unsigned b0, b1, b2, b3;
                ldm4(b0, b1, b2, b3,
                     ksBase + ((np * 16 + kRow) * KPT + s * 8 + kCol) * 4);
                MMA_BF16(c[2 * np][0], c[2 * np][1], c[2 * np][2], c[2 * np][3],
                         aq[s][0], aq[s][1], aq[s][2], aq[s][3], b0, b1);
                MMA_BF16(c[2 * np + 1][0], c[2 * np + 1][1],
                         c[2 * np + 1][2], c[2 * np + 1][3],
                         aq[s][0], aq[s][1], aq[s][2], aq[s][3], b2, b3);
            }
        }

        // ---- mask + online softmax ----
        const int cb = kt * 64 + 2 * tq;
        float mx0 = -1e30f, mx1 = -1e30f;
#pragma unroll
        for (int n = 0; n < 8; n++) {
            int c0 = cb + n * 8, c1 = c0 + 1;
            if (c0 >= len) { c[n][0] = -1e30f; c[n][2] = -1e30f; }
            if (c1 >= len) { c[n][1] = -1e30f; c[n][3] = -1e30f; }
            mx0 = fmaxf(mx0, fmaxf(c[n][0], c[n][1]));
            mx1 = fmaxf(mx1, fmaxf(c[n][2], c[n][3]));
        }
        mx0 = fmaxf(mx0, __shfl_xor_sync(0xffffffffu, mx0, 1));
        mx0 = fmaxf(mx0, __shfl_xor_sync(0xffffffffu, mx0, 2));
        mx1 = fmaxf(mx1, __shfl_xor_sync(0xffffffffu, mx1, 1));
        mx1 = fmaxf(mx1, __shfl_xor_sync(0xffffffffu, mx1, 2));

        float mn0 = fmaxf(mr0, mx0), mn1 = fmaxf(mr1, mx1);
        float al0 = __expf(mr0 - mn0), al1 = __expf(mr1 - mn1);
        float rs0 = 0.f, rs1 = 0.f;
#pragma unroll
        for (int n = 0; n < 8; n++) {
            c[n][0] = __expf(c[n][0] - mn0);
            c[n][1] = __expf(c[n][1] - mn0);
            c[n][2] = __expf(c[n][2] - mn1);
            c[n][3] = __expf(c[n][3] - mn1);
            rs0 += c[n][0] + c[n][1];
            rs1 += c[n][2] + c[n][3];
        }
        rs0 += __shfl_xor_sync(0xffffffffu, rs0, 1);
        rs0 += __shfl_xor_sync(0xffffffffu, rs0, 2);
        rs1 += __shfl_xor_sync(0xffffffffu, rs1, 1);
        rs1 += __shfl_xor_sync(0xffffffffu, rs1, 2);
        lr0 = lr0 * al0 + rs0;
        lr1 = lr1 * al1 + rs1;
        mr0 = mn0; mr1 = mn1;
#pragma unroll
        for (int n = 0; n < 8; n++) {
            O[n][0] *= al0; O[n][1] *= al0;
            O[n][2] *= al1; O[n][3] *= al1;
        }

        // ---- write P packed (per-warp region) ----
#pragma unroll
        for (int n = 0; n < 8; n++) {
            Pw[qid * QP + 4 * n + tq]       = pk2(c[n][0], c[n][1]);
            Pw[(qid + 8) * QP + 4 * n + tq] = pk2(c[n][2], c[n][3]);
        }
        __syncwarp();

        // ---- O += P @ V ----
#pragma unroll
        for (int s = 0; s < 4; s++) {
            unsigned ap0, ap1, ap2, ap3;
            ldm4(ap0, ap1, ap2, ap3, aFrag + s * 8 * 4);
#pragma unroll
            for (int n = 0; n < 8; n++) {
                unsigned b0 = Vs[(s * 8 + tq) * VPT + n * 8 + qid];
                unsigned b1 = Vs[(s * 8 + tq + 4) * VPT + n * 8 + qid];
                MMA_BF16(O[n][0], O[n][1], O[n][2], O[n][3],
                         ap0, ap1, ap2, ap3, b0, b1);
            }
        }
        __syncwarp();
    }

    // ---- epilogue: packed ctx ----
    float inv0 = 1.f / lr0, inv1 = 1.f / lr1;
    int h = bh & 7;
    size_t row0 = (size_t)(b * Sn + qt * 128 + m0 + qid);
#pragma unroll
    for (int n = 0; n < 8; n++) {
        int dp = h * 32 + 4 * n + tq;
        ctxpk[row0 * 256 + dp]       = pk2(O[n][0] * inv0, O[n][1] * inv0);
        ctxpk[(row0 + 8) * 256 + dp] = pk2(O[n][2] * inv1, O[n][3] * inv1);
    }
}

// ============================ add + layernorm ===============================
__device__ __forceinline__ float blk_sum_128(float v, float* red) {
#pragma unroll
    for (int o = 16; o; o >>= 1) v += __shfl_xor_sync(0xffffffffu, v, o);
    __syncthreads();
    if ((threadIdx.x & 31) == 0) red[threadIdx.x >> 5] = v;
    __syncthreads();
    return red[0] + red[1] + red[2] + red[3];
}

__global__ __launch_bounds__(128)
void add_ln_kernel(float* __restrict__ x, uint32_t* __restrict__ xpk,
                   const float* __restrict__ hh,
                   const float* __restrict__ g, const float* __restrict__ be) {
    __shared__ float red[4];
    int row = blockIdx.x;
    int t = threadIdx.x;
    size_t off = (size_t)row * 512 + t * 4;
    float4 xv = *(float4*)(x + off);
    float4 hv = *(const float4*)(hh + off);
    float v0 = xv.x + hv.x, v1 = xv.y + hv.y, v2 = xv.z + hv.z, v3 = xv.w + hv.w;
    float mean = blk_sum_128(v0 + v1 + v2 + v3, red) * (1.f / 512.f);
    float d0 = v0 - mean, d1 = v1 - mean, d2 = v2 - mean, d3 = v3 - mean;
    float var = blk_sum_128(d0 * d0 + d1 * d1 + d2 * d2 + d3 * d3, red) * (1.f / 512.f);
    float rstd = rsqrtf(var + 1e-5f);
    float4 gv = *(const float4*)(g + t * 4);
    float4 bv = *(const float4*)(be + t * 4);
    float4 o;
    o.x = d0 * rstd * gv.x + bv.x;
    o.y = d1 * rstd * gv.y + bv.y;
    o.z = d2 * rstd * gv.z + bv.z;
    o.w = d3 * rstd * gv.w + bv.w;
    *(float4*)(x + off) = o;
    uint2 p;
    p.x = pk2(o.x, o.y);
    p.y = pk2(o.z, o.w);
    *(uint2*)(xpk + (size_t)row * 256 + t * 2) = p;
}

// ============================ final head ====================================
#define HEAD_SMEM (512 * 32 * 4)

__global__ __launch_bounds__(256)
void final_logits_kernel(const float* __restrict__ x, const float* __restrict__ addr,
                         const float* __restrict__ poi, const int* __restrict__ atype,
                         const float* __restrict__ Wa, const float* __restrict__ ba,
                         const float* __restrict__ Wout, const float* __restrict__ Wcomb,
                         const int* __restrict__ dlen, float* __restrict__ logits) {
    extern __shared__ float ws[];
    for (int i = threadIdx.x; i < 512 * 32; i += 256) ws[i] = Wout[i];
    __syncthreads();

    const int warp = threadIdx.x >> 5;
    const int lane = threadIdx.x & 31;
    const float wc = Wcomb[lane];

    for (int tok = blockIdx.x * 8 + warp; tok < BSn; tok += gridDim.x * 8) {
        int b = tok >> 10;
        int s = tok & 1023;
        int t = atype[b];
        float aj = ba[lane]
                 + addr[b]        * Wa[lane]
                 + poi[t * 3 + 0] * Wa[32 + lane]
                 + poi[t * 3 + 1] * Wa[64 + lane]
                 + poi[t * 3 + 2] * Wa[96 + lane];
        const float* xr = x + (size_t)tok * 512;
        float acc = 0.f;
        for (int d0 = 0; d0 < 512; d0 += 32) {
            float xv = xr[d0 + lane];
#pragma unroll
            for (int j = 0; j < 32; j++)
                acc += __shfl_sync(0xffffffffu, xv, j) * ws[(d0 + j) * 32 + lane];
        }
        float tv = tanhf(acc + aj) * wc;
#pragma unroll
        for (int o = 16; o; o >>= 1) tv += __shfl_xor_sync(0xffffffffu, tv, o);
        if (lane == 0) logits[tok] = (s < dlen[b]) ? tv : -1e9f;
    }
}

__global__ __launch_bounds__(256)
void logsoftmax_kernel(const float* __restrict__ logits, const int* __restrict__ dlen,
                       float* __restrict__ out) {
    __shared__ float red[8];
    int b = blockIdx.x;
    int len = dlen[b];
    const float* lg = logits + (size_t)b * Sn;
    float mx = -1e30f;
    for (int s = threadIdx.x; s < len; s += 256) mx = fmaxf(mx, lg[s]);
#pragma unroll
    for (int o = 16; o; o >>= 1) mx = fmaxf(mx, __shfl_xor_sync(0xffffffffu, mx, o));
    if ((threadIdx.x & 31) == 0) red[threadIdx.x >> 5] = mx;
    __syncthreads();
    mx = red[0];
#pragma unroll
    for (int w = 1; w < 8; w++) mx = fmaxf(mx, red[w]);
    __syncthreads();
    float sum = 0.f;
    for (int s = threadIdx.x; s < len; s += 256) sum += expf(lg[s] - mx);
#pragma unroll
    for (int o = 16; o; o >>= 1) sum += __shfl_xor_sync(0xffffffffu, sum, o);
    if ((threadIdx.x & 31) == 0) red[threadIdx.x >> 5] = sum;
    __syncthreads();
    sum = red[0] + red[1] + red[2] + red[3] + red[4] + red[5] + red[6] + red[7];
    float lse = logf(sum) + mx;
    for (int s = threadIdx.x; s < Sn; s += 256)
        out[(size_t)b * Sn + s] = (s < len) ? (lg[s] - lse) : 0.f;
}

// ============================ launch ========================================
extern "C" void kernel_launch(void* const* d_in, const int* in_sizes, int n_in,
                              void* d_out, int out_size) {
    const float* addr  = (const float*)d_in[0];
    const float* loc   = (const float*)d_in[1];
    const float* tdist = (const float*)d_in[2];
    const float* Wtd   = (const float*)d_in[3];
    const float* btd   = (const float*)d_in[4];
    const float* Wemb  = (const float*)d_in[5];
    const float* bemb  = (const float*)d_in[6];
    const float* Wqkv  = (const float*)d_in[7];
    const float* bqkv  = (const float*)d_in[8];
    const float* Wo    = (const float*)d_in[9];
    const float* bo    = (const float*)d_in[10];
    const float* ln1g  = (const float*)d_in[11];
    const float* ln1b  = (const float*)d_in[12];
    const float* W1    = (const float*)d_in[13];
    const float* b1    = (const float*)d_in[14];
    const float* W2    = (const float*)d_in[15];
    const float* b2    = (const float*)d_in[16];
    const float* ln2g  = (const float*)d_in[17];
    const float* ln2b  = (const float*)d_in[18];
    const float* poi   = (const float*)d_in[19];
    const float* Wa    = (const float*)d_in[20];
    const float* ba    = (const float*)d_in[21];
    const float* Wout  = (const float*)d_in[22];
    const float* Wcomb = (const float*)d_in[23];
    const int*   atype = (const int*)d_in[24];
    const int*   dlen  = (const int*)d_in[25];
    float* out = (float*)d_out;

    float *x, *t1, *vtmp, *lg;
    uint32_t *xpk, *qpk, *kpk, *vpk, *ctxpk, *t2pk, *wqkv, *wo, *w1, *w2;
    cudaGetSymbolAddress((void**)&x,     g_x);
    cudaGetSymbolAddress((void**)&xpk,   g_xpk);
    cudaGetSymbolAddress((void**)&qpk,   g_qpk);
    cudaGetSymbolAddress((void**)&kpk,   g_kpk);
    cudaGetSymbolAddress((void**)&vtmp,  g_vtmp);
    cudaGetSymbolAddress((void**)&vpk,   g_vpk);
    cudaGetSymbolAddress((void**)&ctxpk, g_ctxpk);
    cudaGetSymbolAddress((void**)&t1,    g_t1);
    cudaGetSymbolAddress((void**)&t2pk,  g_t2pk);
    cudaGetSymbolAddress((void**)&wqkv,  g_wqkv);
    cudaGetSymbolAddress((void**)&wo,    g_wo);
    cudaGetSymbolAddress((void**)&w1,    g_w1);
    cudaGetSymbolAddress((void**)&w2,    g_w2);
    cudaGetSymbolAddress((void**)&lg,    g_logits);

    cudaFuncSetAttribute(flash_bf16_kernel,
                         cudaFuncAttributeMaxDynamicSharedMemorySize, FLASH_SMEM);
    cudaFuncSetAttribute(final_logits_kernel,
                         cudaFuncAttributeMaxDynamicSharedMemorySize, HEAD_SMEM);

    // pack all weights: [L][2Kp][N] -> [L][N][Kp] bf16x2, tiled transpose
    pack_w_kernel<<<dim3(8, 48, Ln), 256>>>(Wqkv, wqkv, 256, 1536);
    pack_w_kernel<<<dim3(8, 16, Ln), 256>>>(Wo, wo, 256, 512);
    pack_w_kernel<<<dim3(8, 16, Ln), 256>>>(W1, w1, 256, 512);
    pack_w_kernel<<<dim3(8, 16, Ln), 256>>>(W2, w2, 256, 512);

    embed_kernel<<<BSn, 128>>>(loc, tdist, Wtd, btd, Wemb, bemb, x, xpk);

    for (int l = 0; l < Ln; l++) {
        bf16_gemm<2><<<dim3(12, 256), 256>>>(
            xpk, wqkv + (size_t)l * 1536 * 256, bqkv + l * 1536,
            nullptr, nullptr, qpk, kpk, vtmp, BSn, 1536, 256);
        repack_v_kernel<<<256 * 8, 256>>>(vtmp, vpk);
        flash_bf16_kernel<<<dim3(8, Bn * Hn), 256, FLASH_SMEM>>>(qpk, kpk, vpk,
                                                                 ctxpk, dlen);
        bf16_gemm<0><<<dim3(4, 256), 256>>>(
            ctxpk, wo + (size_t)l * 512 * 256, bo + l * 512,
            t1, nullptr, nullptr, nullptr, nullptr, BSn, 512, 256);
        add_ln_kernel<<<BSn, 128>>>(x, xpk, t1, ln1g + l * 512, ln1b + l * 512);
        bf16_gemm<1><<<dim3(4, 256), 256>>>(
            xpk, w1 + (size_t)l * 512 * 256, b1 + l * 512,
            nullptr, t2pk, nullptr, nullptr, nullptr, BSn, 512, 256);
        bf16_gemm<0><<<dim3(4, 256), 256>>>(
            t2pk, w2 + (size_t)l * 512 * 256, b2 + l * 512,
            t1, nullptr, nullptr, nullptr, nullptr, BSn, 512, 256);
        add_ln_kernel<<<BSn, 128>>>(x, xpk, t1, ln2g + l * 512, ln2b + l * 512);
    }

    final_logits_kernel<<<512, 256, HEAD_SMEM>>>(x, addr, poi, atype, Wa, ba,
                                                 Wout, Wcomb, dlen, lg);
    logsoftmax_kernel<<<Bn, 256>>>(lg, dlen, out);
}

// round 10
// speedup vs baseline: 1.6221x; 1.6221x over previous
#include <cuda_runtime.h>
#include <math.h>
#include <stdint.h>

#define Bn   32
#define Sn   1024
#define Dn   512
#define Hn   8
#define Ln   4
#define BSn  (Bn*Sn)

// ------------------------- scratch (device globals) -------------------------
__device__ float    g_x[(size_t)BSn * Dn];
__device__ uint32_t g_xpk[(size_t)BSn * 256];
__device__ uint32_t g_qpk[(size_t)256 * 1024 * 32];
__device__ uint32_t g_kpk[(size_t)256 * 1024 * 32];
__device__ float    g_vtmp[(size_t)256 * 1024 * 64];
__device__ uint32_t g_vpk[(size_t)256 * 512 * 64];
__device__ uint32_t g_ctxpk[(size_t)BSn * 256];
__device__ float    g_t1[(size_t)BSn * Dn];
__device__ uint32_t g_t2pk[(size_t)BSn * 256];
__device__ uint32_t g_wqkv[(size_t)Ln * 256 * 1536];
__device__ uint32_t g_wo[(size_t)Ln * 256 * 512];
__device__ uint32_t g_w1[(size_t)Ln * 256 * 512];
__device__ uint32_t g_w2[(size_t)Ln * 256 * 512];
__device__ float    g_logits[BSn];

// pack two fp32 into bf16x2: low half = first arg (even k), high = second
__device__ __forceinline__ uint32_t pk2(float lo, float hi) {
    uint32_t r;
    asm("cvt.rn.bf16x2.f32 %0, %1, %2;" : "=r"(r) : "f"(hi), "f"(lo));
    return r;
}

__device__ __forceinline__ void cpa16(uint32_t dst, const void* src) {
    asm volatile("cp.async.cg.shared.global [%0], [%1], 16;" :: "r"(dst), "l"(src));
}
#define CP_COMMIT() asm volatile("cp.async.commit_group;")
#define CP_WAIT(N)  asm volatile("cp.async.wait_group %0;" :: "n"(N))

#define MMA_BF16(C0,C1,C2,C3,A0,A1,A2,A3,B0,B1)                              \
    asm volatile(                                                            \
        "mma.sync.aligned.m16n8k16.row.col.f32.bf16.bf16.f32 "               \
        "{%0,%1,%2,%3}, {%4,%5,%6,%7}, {%8,%9}, {%0,%1,%2,%3};"              \
        : "+f"(C0), "+f"(C1), "+f"(C2), "+f"(C3)                             \
        : "r"(A0), "r"(A1), "r"(A2), "r"(A3), "r"(B0), "r"(B1))

// ============================ weight pack ===================================
__global__ void pack_w_kernel(const float* __restrict__ src,
                              uint32_t* __restrict__ dst, int KpT, int N) {
    int idx = blockIdx.x * 256 + threadIdx.x;
    if (idx >= KpT * N) return;
    int kp = idx / N;
    int n  = idx - kp * N;
    dst[idx] = pk2(src[(size_t)(2 * kp) * N + n], src[(size_t)(2 * kp + 1) * N + n]);
}

// ============================ embed =========================================
__global__ void embed_kernel(const float* __restrict__ loc,
                             const float* __restrict__ tdist,
                             const float* __restrict__ Wtd,
                             const float* __restrict__ btd,
                             const float* __restrict__ Wemb,
                             const float* __restrict__ bemb,
                             float* __restrict__ x,
                             uint32_t* __restrict__ xpk) {
    int tok = blockIdx.x;
    const float* lp = loc + (size_t)tok * 16;
    const float* tp = tdist + (size_t)tok * 8;
    float in[19];
#pragma unroll
    for (int i = 0; i < 16; i++) in[i] = lp[i];
#pragma unroll
    for (int j = 0; j < 3; j++) {
        float s = btd[j];
#pragma unroll
        for (int i = 0; i < 8; i++) s += tp[i] * Wtd[i * 3 + j];
        in[16 + j] = s;
    }
    int d = threadIdx.x * 4;
    float4 acc = *(const float4*)(bemb + d);
#pragma unroll
    for (int i = 0; i < 19; i++) {
        float4 w = *(const float4*)(Wemb + i * 512 + d);
        float s = in[i];
        acc.x += s * w.x; acc.y += s * w.y; acc.z += s * w.z; acc.w += s * w.w;
    }
    *(float4*)(x + (size_t)tok * 512 + d) = acc;
    uint2 p;
    p.x = pk2(acc.x, acc.y);
    p.y = pk2(acc.z, acc.w);
    *(uint2*)(xpk + (size_t)tok * 256 + threadIdx.x * 2) = p;
}

// ============================ bf16 tensor-core GEMM =========================
// A packed [M][Kp] bf16x2 (k-pairs), W packed [Kp][N].
// Block 128x128, chunk K=16 (8 k-pairs), 8 warps 2x4, warp tile 64x32.
// MODE 0: fp32 out. MODE 1: relu + packed bf16 out. MODE 2: QKV special.
// Early-exits whole m-tile when all its rows are beyond data_length.
template <int MODE>
__global__ __launch_bounds__(256)
void bf16_gemm(const uint32_t* __restrict__ Apk, const uint32_t* __restrict__ Wpk,
               const float* __restrict__ bias,
               float* __restrict__ Cf, uint32_t* __restrict__ Cpk,
               uint32_t* __restrict__ Qpk, uint32_t* __restrict__ Kpk,
               float* __restrict__ Vtmp,
               const int* __restrict__ dlen,
               int M, int N, int Kp) {
    const int bm = blockIdx.y * 128;
    if ((bm & 1023) >= dlen[bm >> 10]) return;   // whole tile invalid

    __shared__ uint32_t As[2][128 * 12];   // [m][kpair] pitch 12
    __shared__ uint32_t Ws[2][8 * 136];    // [kpair][n] pitch 136

    const int tid  = threadIdx.x;
    const int warp = tid >> 5;
    const int lane = tid & 31;
    const int wm = warp >> 2;
    const int wn = warp & 3;
    const int qid = lane >> 2;
    const int tq  = lane & 3;

    const int bn = blockIdx.x * 128;

    const int arow = tid >> 1;
    const int akp  = (tid & 1) << 2;       // 0 or 4
    const int wkp  = tid >> 5;             // 0..7
    const int wn4  = (tid & 31) << 2;      // 0..124

    const uint32_t* Ag = Apk + (size_t)(bm + arow) * Kp + akp;
    const uint32_t* Wg = Wpk + (size_t)wkp * N + bn + wn4;

    uint32_t aAd[2], aWd[2];
    {
        uint32_t a0 = (uint32_t)__cvta_generic_to_shared(&As[0][0]);
        uint32_t a1 = (uint32_t)__cvta_generic_to_shared(&As[1][0]);
        uint32_t w0 = (uint32_t)__cvta_generic_to_shared(&Ws[0][0]);
        uint32_t w1 = (uint32_t)__cvta_generic_to_shared(&Ws[1][0]);
        aAd[0] = a0 + (arow * 12 + akp) * 4;
        aAd[1] = a1 + (arow * 12 + akp) * 4;
        aWd[0] = w0 + (wkp * 136 + wn4) * 4;
        aWd[1] = w1 + (wkp * 136 + wn4) * 4;
    }

    // prologue: chunk 0
    cpa16(aAd[0], Ag);
    cpa16(aWd[0], Wg);
    CP_COMMIT();

    float acc[4][4][4];
#pragma unroll
    for (int i = 0; i < 4; i++)
#pragma unroll
        for (int j = 0; j < 4; j++)
#pragma unroll
            for (int c = 0; c < 4; c++) acc[i][j][c] = 0.f;

    const int nck = Kp >> 3;
    for (int kc = 0; kc < nck; kc++) {
        const int s = kc & 1;
        if (kc + 1 < nck) {
            cpa16(aAd[s ^ 1], Ag + (kc + 1) * 8);
            cpa16(aWd[s ^ 1], Wg + (size_t)(kc + 1) * 8 * N);
            CP_COMMIT();
            CP_WAIT(1);
        } else {
            CP_WAIT(0);
        }
        __syncthreads();

        const uint32_t* as_ = As[s];
        const uint32_t* ws_ = Ws[s];
        unsigned a[4][4], b[4][2];
#pragma unroll
        for (int am = 0; am < 4; am++) {
            int m = wm * 64 + am * 16;
            a[am][0] = as_[(m + qid) * 12 + tq];
            a[am][1] = as_[(m + qid + 8) * 12 + tq];
            a[am][2] = as_[(m + qid) * 12 + tq + 4];
            a[am][3] = as_[(m + qid + 8) * 12 + tq + 4];
        }
#pragma unroll
        for (int an = 0; an < 4; an++) {
            int n0 = wn * 32 + an * 8;
            b[an][0] = ws_[tq * 136 + n0 + qid];
            b[an][1] = ws_[(tq + 4) * 136 + n0 + qid];
        }
#pragma unroll
        for (int am = 0; am < 4; am++)
#pragma unroll
            for (int an = 0; an < 4; an++)
                MMA_BF16(acc[am][an][0], acc[am][an][1],
                         acc[am][an][2], acc[am][an][3],
                         a[am][0], a[am][1], a[am][2], a[am][3],
                         b[an][0], b[an][1]);
        __syncthreads();
    }

    // epilogue
#pragma unroll
    for (int am = 0; am < 4; am++) {
        int r0 = bm + wm * 64 + am * 16 + qid;
#pragma unroll
        for (int an = 0; an < 4; an++) {
            int col = bn + wn * 32 + an * 8 + 2 * tq;
            float b0 = bias[col], b1 = bias[col + 1];
            float v0 = acc[am][an][0] + b0;
            float v1 = acc[am][an][1] + b1;
            float v2 = acc[am][an][2] + b0;
            float v3 = acc[am][an][3] + b1;
            if (MODE == 0) {
                *(float2*)(Cf + (size_t)r0 * N + col)       = make_float2(v0, v1);
                *(float2*)(Cf + (size_t)(r0 + 8) * N + col) = make_float2(v2, v3);
            } else if (MODE == 1) {
                v0 = fmaxf(v0, 0.f); v1 = fmaxf(v1, 0.f);
                v2 = fmaxf(v2, 0.f); v3 = fmaxf(v3, 0.f);
                Cpk[(size_t)r0 * (N >> 1) + (col >> 1)]       = pk2(v0, v1);
                Cpk[(size_t)(r0 + 8) * (N >> 1) + (col >> 1)] = pk2(v2, v3);
            } else {
                int bb = r0 >> 10;
                int sr = r0 & 1023;
                int h  = (col >> 6) & 7;
                size_t bh = (size_t)(bb * 8 + h);
                if (col < 512) {
                    v0 *= 0.125f; v1 *= 0.125f; v2 *= 0.125f; v3 *= 0.125f;
                    size_t base = (bh * 1024 + sr) * 32 + ((col & 63) >> 1);
                    Qpk[base]            = pk2(v0, v1);
                    Qpk[base + 8 * 32]   = pk2(v2, v3);
                } else if (col < 1024) {
                    size_t base = (bh * 1024 + sr) * 32 + ((col & 63) >> 1);
                    Kpk[base]            = pk2(v0, v1);
                    Kpk[base + 8 * 32]   = pk2(v2, v3);
                } else {
                    size_t base = (bh * 1024 + sr) * 64 + (col & 63);
                    *(float2*)(Vtmp + base)            = make_float2(v0, v1);
                    *(float2*)(Vtmp + base + 8 * 64)   = make_float2(v2, v3);
                }
            }
        }
    }
}

// ============================ V repack (key-pair packing) ===================
__global__ __launch_bounds__(256)
void repack_v_kernel(const float* __restrict__ Vtmp, uint32_t* __restrict__ Vpk,
                     const int* __restrict__ dlen) {
    int bh  = blockIdx.x >> 3;
    int kp0 = (blockIdx.x & 7) * 64;
    if (kp0 * 2 >= dlen[bh >> 3]) return;         // all keys of this tile invalid
    const float* src = Vtmp + (size_t)bh * 1024 * 64;
    uint32_t* dst = Vpk + ((size_t)bh * 512 + kp0) * 64;
    for (int i = threadIdx.x; i < 64 * 64; i += 256) {
        int kpl = i >> 6;
        int d   = i & 63;
        int key0 = 2 * (kp0 + kpl);
        dst[(size_t)kpl * 64 + d] = pk2(src[(size_t)key0 * 64 + d],
                                        src[(size_t)(key0 + 1) * 64 + d]);
    }
}

// ============================ flash attention (bf16 mma) ====================
#define QP  36
#define KPT 36
#define VPT 72
#define KTILE (64 * KPT)
#define VTILE (32 * VPT)
#define FSTG (KTILE + VTILE)
#define QTILE (128 * QP)
#define FLASH_SMEM ((2 * FSTG + QTILE) * 4)

__global__ __launch_bounds__(256)
void flash_bf16_kernel(const uint32_t* __restrict__ Qpk,
                       const uint32_t* __restrict__ Kpk,
                       const uint32_t* __restrict__ Vpk,
                       uint32_t* __restrict__ ctxpk,
                       const int* __restrict__ dlen) {
    extern __shared__ uint32_t smu[];

    const int qt = blockIdx.x;
    const int bh = blockIdx.y;
    const int b  = bh >> 3;
    const int len = dlen[b];
    if (qt * 128 >= len) return;                  // all queries invalid
    const int nk = (len + 63) >> 6;

    const int tid = threadIdx.x;
    const int warp = tid >> 5;
    const int lane = tid & 31;
    const int qid = lane >> 2;
    const int tq  = lane & 3;
    const int m0  = warp * 16;

    const uint32_t* Qg = Qpk + ((size_t)bh * 1024 + qt * 128) * 32;
    const uint32_t* Kg = Kpk + (size_t)bh * 1024 * 32;
    const uint32_t* Vg = Vpk + (size_t)bh * 512 * 64;

    uint32_t* Qs = smu + 2 * FSTG;
    uint32_t smbase = (uint32_t)__cvta_generic_to_shared(smu);
    uint32_t qbase  = smbase + 2 * FSTG * 4;

    // group 1: Q tile
#pragma unroll
    for (int u = 0; u < 4; u++) {
        int f = tid + u * 256;
        int r = f >> 3, c4 = (f & 7) << 2;
        cpa16(qbase + (r * QP + c4) * 4, Qg + (size_t)r * 32 + c4);
    }
    CP_COMMIT();
    // group 2: K/V tile 0
    {
        uint32_t kd = smbase, vd = smbase + KTILE * 4;
#pragma unroll
        for (int u = 0; u < 2; u++) {
            int f = tid + u * 256;
            int rk = f >> 3, ck = (f & 7) << 2;
            cpa16(kd + (rk * KPT + ck) * 4, Kg + (size_t)rk * 32 + ck);
            int rv = f >> 4, cv = (f & 15) << 2;
            cpa16(vd + (rv * VPT + cv) * 4, Vg + (size_t)rv * 64 + cv);
        }
        CP_COMMIT();
    }
    CP_WAIT(1);
    __syncthreads();

    // Q fragments: 4 d-chunks of k16
    unsigned aq[4][4];
#pragma unroll
    for (int s = 0; s < 4; s++) {
        aq[s][0] = Qs[(m0 + qid) * QP + s * 8 + tq];
        aq[s][1] = Qs[(m0 + qid + 8) * QP + s * 8 + tq];
        aq[s][2] = Qs[(m0 + qid) * QP + s * 8 + tq + 4];
        aq[s][3] = Qs[(m0 + qid + 8) * QP + s * 8 + tq + 4];
    }
    uint32_t* Pw = Qs + m0 * QP;     // per-warp P tile [16][QP]

    float mr0 = -1e30f, mr1 = -1e30f, lr0 = 0.f, lr1 = 0.f;
    float O[8][4];
#pragma unroll
    for (int n = 0; n < 8; n++)
#pragma unroll
        for (int c = 0; c < 4; c++) O[n][c] = 0.f;

    for (int kt = 0; kt < nk; kt++) {
        __syncthreads();
        if (kt + 1 < nk) {
            uint32_t sb = smbase + ((kt + 1) & 1) * FSTG * 4;
            uint32_t kd = sb, vd = sb + KTILE * 4;
            const uint32_t* kg = Kg + (size_t)(kt + 1) * 64 * 32;
            const uint32_t* vg = Vg + (size_t)(kt + 1) * 32 * 64;
#pragma unroll
            for (int u = 0; u < 2; u++) {
                int f = tid + u * 256;
                int rk = f >> 3, ck = (f & 7) << 2;
                cpa16(kd + (rk * KPT + ck) * 4, kg + (size_t)rk * 32 + ck);
                int rv = f >> 4, cv = (f & 15) << 2;
                cpa16(vd + (rv * VPT + cv) * 4, vg + (size_t)rv * 64 + cv);
            }
            CP_COMMIT();
            CP_WAIT(1);
        } else {
            CP_WAIT(0);
        }
        __syncthreads();

        const uint32_t* Ks = smu + (kt & 1) * FSTG;
        const uint32_t* Vs = Ks + KTILE;

        // ---- S = Q @ K^T (Q pre-scaled) ----
        float c[8][4];
#pragma unroll
        for (int n = 0; n < 8; n++)
#pragma unroll
            for (int j = 0; j < 4; j++) c[n][j] = 0.f;

#pragma unroll
        for (int s = 0; s < 4; s++) {
#pragma unroll
            for (int n = 0; n < 8; n++) {
                unsigned b0 = Ks[(n * 8 + qid) * KPT + s * 8 + tq];
                unsigned b1 = Ks[(n * 8 + qid) * KPT + s * 8 + tq + 4];
                MMA_BF16(c[n][0], c[n][1], c[n][2], c[n][3],
                         aq[s][0], aq[s][1], aq[s][2], aq[s][3], b0, b1);
            }
        }

        // ---- mask + online softmax (mask ASSIGNS, so stale-K NaN can't leak) ----
        const int cb = kt * 64 + 2 * tq;
        float mx0 = -1e30f, mx1 = -1e30f;
#pragma unroll
        for (int n = 0; n < 8; n++) {
            int c0 = cb + n * 8, c1 = c0 + 1;
            if (c0 >= len) { c[n][0] = -1e30f; c[n][2] = -1e30f; }
            if (c1 >= len) { c[n][1] = -1e30f; c[n][3] = -1e30f; }
            mx0 = fmaxf(mx0, fmaxf(c[n][0], c[n][1]));
            mx1 = fmaxf(mx1, fmaxf(c[n][2], c[n][3]));
        }
        mx0 = fmaxf(mx0, __shfl_xor_sync(0xffffffffu, mx0, 1));
        mx0 = fmaxf(mx0, __shfl_xor_sync(0xffffffffu, mx0, 2));
        mx1 = fmaxf(mx1, __shfl_xor_sync(0xffffffffu, mx1, 1));
        mx1 = fmaxf(mx1, __shfl_xor_sync(0xffffffffu, mx1, 2));

        float mn0 = fmaxf(mr0, mx0), mn1 = fmaxf(mr1, mx1);
        float al0 = __expf(mr0 - mn0), al1 = __expf(mr1 - mn1);
        float rs0 = 0.f, rs1 = 0.f;
#pragma unroll
        for (int n = 0; n < 8; n++) {
            c[n][0] = __expf(c[n][0] - mn0);
            c[n][1] = __expf(c[n][1] - mn0);
            c[n][2] = __expf(c[n][2] - mn1);
            c[n][3] = __expf(c[n][3] - mn1);
            rs0 += c[n][0] + c[n][1];
            rs1 += c[n][2] + c[n][3];
        }
        rs0 += __shfl_xor_sync(0xffffffffu, rs0, 1);
        rs0 += __shfl_xor_sync(0xffffffffu, rs0, 2);
        rs1 += __shfl_xor_sync(0xffffffffu, rs1, 1);
        rs1 += __shfl_xor_sync(0xffffffffu, rs1, 2);
        lr0 = lr0 * al0 + rs0;
        lr1 = lr1 * al1 + rs1;
        mr0 = mn0; mr1 = mn1;
#pragma unroll
        for (int n = 0; n < 8; n++) {
            O[n][0] *= al0; O[n][1] *= al0;
            O[n][2] *= al1; O[n][3] *= al1;
        }

        // ---- write P packed (per-warp region) ----
#pragma unroll
        for (int n = 0; n < 8; n++) {
            Pw[qid * QP + 4 * n + tq]       = pk2(c[n][0], c[n][1]);
            Pw[(qid + 8) * QP + 4 * n + tq] = pk2(c[n][2], c[n][3]);
        }
        __syncwarp();

        // ---- O += P @ V ----
#pragma unroll
        for (int s = 0; s < 4; s++) {
            unsigned ap0 = Pw[qid * QP + s * 8 + tq];
            unsigned ap1 = Pw[(qid + 8) * QP + s * 8 + tq];
            unsigned ap2 = Pw[qid * QP + s * 8 + tq + 4];
            unsigned ap3 = Pw[(qid + 8) * QP + s * 8 + tq + 4];
#pragma unroll
            for (int n = 0; n < 8; n++) {
                unsigned b0 = Vs[(s * 8 + tq) * VPT + n * 8 + qid];
                unsigned b1 = Vs[(s * 8 + tq + 4) * VPT + n * 8 + qid];
                MMA_BF16(O[n][0], O[n][1], O[n][2], O[n][3],
                         ap0, ap1, ap2, ap3, b0, b1);
            }
        }
        __syncwarp();
    }

    // ---- epilogue: packed ctx ----
    float inv0 = 1.f / lr0, inv1 = 1.f / lr1;
    int h = bh & 7;
    size_t row0 = (size_t)(b * Sn + qt * 128 + m0 + qid);
#pragma unroll
    for (int n = 0; n < 8; n++) {
        int dp = h * 32 + 4 * n + tq;
        ctxpk[row0 * 256 + dp]       = pk2(O[n][0] * inv0, O[n][1] * inv0);
        ctxpk[(row0 + 8) * 256 + dp] = pk2(O[n][2] * inv1, O[n][3] * inv1);
    }
}

// ============================ add + layernorm ===============================
__device__ __forceinline__ float blk_sum_128(float v, float* red) {
#pragma unroll
    for (int o = 16; o; o >>= 1) v += __shfl_xor_sync(0xffffffffu, v, o);
    __syncthreads();
    if ((threadIdx.x & 31) == 0) red[threadIdx.x >> 5] = v;
    __syncthreads();
    return red[0] + red[1] + red[2] + red[3];
}

__global__ __launch_bounds__(128)
void add_ln_kernel(float* __restrict__ x, uint32_t* __restrict__ xpk,
                   const float* __restrict__ hh,
                   const float* __restrict__ g, const float* __restrict__ be,
                   const int* __restrict__ dlen) {
    int row = blockIdx.x;
    if ((row & 1023) >= dlen[row >> 10]) return;
    __shared__ float red[4];
    int t = threadIdx.x;
    size_t off = (size_t)row * 512 + t * 4;
    float4 xv = *(float4*)(x + off);
    float4 hv = *(const float4*)(hh + off);
    float v0 = xv.x + hv.x, v1 = xv.y + hv.y, v2 = xv.z + hv.z, v3 = xv.w + hv.w;
    float mean = blk_sum_128(v0 + v1 + v2 + v3, red) * (1.f / 512.f);
    float d0 = v0 - mean, d1 = v1 - mean, d2 = v2 - mean, d3 = v3 - mean;
    float var = blk_sum_128(d0 * d0 + d1 * d1 + d2 * d2 + d3 * d3, red) * (1.f / 512.f);
    float rstd = rsqrtf(var + 1e-5f);
    float4 gv = *(const float4*)(g + t * 4);
    float4 bv = *(const float4*)(be + t * 4);
    float4 o;
    o.x = d0 * rstd * gv.x + bv.x;
    o.y = d1 * rstd * gv.y + bv.y;
    o.z = d2 * rstd * gv.z + bv.z;
    o.w = d3 * rstd * gv.w + bv.w;
    *(float4*)(x + off) = o;
    uint2 p;
    p.x = pk2(o.x, o.y);
    p.y = pk2(o.z, o.w);
    *(uint2*)(xpk + (size_t)row * 256 + t * 2) = p;
}

// ============================ final head ====================================
#define HEAD_SMEM (512 * 32 * 4)

__global__ __launch_bounds__(256)
void final_logits_kernel(const float* __restrict__ x, const float* __restrict__ addr,
                         const float* __restrict__ poi, const int* __restrict__ atype,
                         const float* __restrict__ Wa, const float* __restrict__ ba,
                         const float* __restrict__ Wout, const float* __restrict__ Wcomb,
                         const int* __restrict__ dlen, float* __restrict__ logits) {
    extern __shared__ float ws[];
    for (int i = threadIdx.x; i < 512 * 32; i += 256) ws[i] = Wout[i];
    __syncthreads();

    const int warp = threadIdx.x >> 5;
    const int lane = threadIdx.x & 31;
    const float wc = Wcomb[lane];

    for (int tok = blockIdx.x * 8 + warp; tok < BSn; tok += gridDim.x * 8) {
        int b = tok >> 10;
        int s = tok & 1023;
        if (s >= dlen[b]) continue;              // invalid: logits never read
        int t = atype[b];
        float aj = ba[lane]
                 + addr[b]        * Wa[lane]
                 + poi[t * 3 + 0] * Wa[32 + lane]
                 + poi[t * 3 + 1] * Wa[64 + lane]
                 + poi[t * 3 + 2] * Wa[96 + lane];
        const float* xr = x + (size_t)tok * 512;
        float acc = 0.f;
        for (int d0 = 0; d0 < 512; d0 += 32) {
            float xv = xr[d0 + lane];
#pragma unroll
            for (int j = 0; j < 32; j++)
                acc += __shfl_sync(0xffffffffu, xv, j) * ws[(d0 + j) * 32 + lane];
        }
        float tv = tanhf(acc + aj) * wc;
#pragma unroll
        for (int o = 16; o; o >>= 1) tv += __shfl_xor_sync(0xffffffffu, tv, o);
        if (lane == 0) logits[tok] = tv;
    }
}

__global__ __launch_bounds__(256)
void logsoftmax_kernel(const float* __restrict__ logits, const int* __restrict__ dlen,
                       float* __restrict__ out) {
    __shared__ float red[8];
    int b = blockIdx.x;
    int len = dlen[b];
    const float* lg = logits + (size_t)b * Sn;
    float mx = -1e30f;
    for (int s = threadIdx.x; s < len; s += 256) mx = fmaxf(mx, lg[s]);
#pragma unroll
    for (int o = 16; o; o >>= 1) mx = fmaxf(mx, __shfl_xor_sync(0xffffffffu, mx, o));
    if ((threadIdx.x & 31) == 0) red[threadIdx.x >> 5] = mx;
    __syncthreads();
    mx = red[0];
#pragma unroll
    for (int w = 1; w < 8; w++) mx = fmaxf(mx, red[w]);
    __syncthreads();
    float sum = 0.f;
    for (int s = threadIdx.x; s < len; s += 256) sum += expf(lg[s] - mx);
#pragma unroll
    for (int o = 16; o; o >>= 1) sum += __shfl_xor_sync(0xffffffffu, sum, o);
    if ((threadIdx.x & 31) == 0) red[threadIdx.x >> 5] = sum;
    __syncthreads();
    sum = red[0] + red[1] + red[2] + red[3] + red[4] + red[5] + red[6] + red[7];
    float lse = logf(sum) + mx;
    for (int s = threadIdx.x; s < Sn; s += 256)
        out[(size_t)b * Sn + s] = (s < len) ? (lg[s] - lse) : 0.f;
}

// ============================ launch ========================================
extern "C" void kernel_launch(void* const* d_in, const int* in_sizes, int n_in,
                              void* d_out, int out_size) {
    const float* addr  = (const float*)d_in[0];
    const float* loc   = (const float*)d_in[1];
    const float* tdist = (const float*)d_in[2];
    const float* Wtd   = (const float*)d_in[3];
    const float* btd   = (const float*)d_in[4];
    const float* Wemb  = (const float*)d_in[5];
    const float* bemb  = (const float*)d_in[6];
    const float* Wqkv  = (const float*)d_in[7];
    const float* bqkv  = (const float*)d_in[8];
    const float* Wo    = (const float*)d_in[9];
    const float* bo    = (const float*)d_in[10];
    const float* ln1g  = (const float*)d_in[11];
    const float* ln1b  = (const float*)d_in[12];
    const float* W1    = (const float*)d_in[13];
    const float* b1    = (const float*)d_in[14];
    const float* W2    = (const float*)d_in[15];
    const float* b2    = (const float*)d_in[16];
    const float* ln2g  = (const float*)d_in[17];
    const float* ln2b  = (const float*)d_in[18];
    const float* poi   = (const float*)d_in[19];
    const float* Wa    = (const float*)d_in[20];
    const float* ba    = (const float*)d_in[21];
    const float* Wout  = (const float*)d_in[22];
    const float* Wcomb = (const float*)d_in[23];
    const int*   atype = (const int*)d_in[24];
    const int*   dlen  = (const int*)d_in[25];
    float* out = (float*)d_out;

    float *x, *t1, *vtmp, *lg;
    uint32_t *xpk, *qpk, *kpk, *vpk, *ctxpk, *t2pk, *wqkv, *wo, *w1, *w2;
    cudaGetSymbolAddress((void**)&x,     g_x);
    cudaGetSymbolAddress((void**)&xpk,   g_xpk);
    cudaGetSymbolAddress((void**)&qpk,   g_qpk);
    cudaGetSymbolAddress((void**)&kpk,   g_kpk);
    cudaGetSymbolAddress((void**)&vtmp,  g_vtmp);
    cudaGetSymbolAddress((void**)&vpk,   g_vpk);
    cudaGetSymbolAddress((void**)&ctxpk, g_ctxpk);
    cudaGetSymbolAddress((void**)&t1,    g_t1);
    cudaGetSymbolAddress((void**)&t2pk,  g_t2pk);
    cudaGetSymbolAddress((void**)&wqkv,  g_wqkv);
    cudaGetSymbolAddress((void**)&wo,    g_wo);
    cudaGetSymbolAddress((void**)&w1,    g_w1);
    cudaGetSymbolAddress((void**)&w2,    g_w2);
    cudaGetSymbolAddress((void**)&lg,    g_logits);

    cudaFuncSetAttribute(flash_bf16_kernel,
                         cudaFuncAttributeMaxDynamicSharedMemorySize, FLASH_SMEM);
    cudaFuncSetAttribute(final_logits_kernel,
                         cudaFuncAttributeMaxDynamicSharedMemorySize, HEAD_SMEM);

    // pack all weights (bf16x2 along K)
    pack_w_kernel<<<(Ln * 256 * 1536 + 255) / 256, 256>>>(Wqkv, wqkv, Ln * 256, 1536);
    pack_w_kernel<<<(Ln * 256 * 512 + 255) / 256, 256>>>(Wo, wo, Ln * 256, 512);
    pack_w_kernel<<<(Ln * 256 * 512 + 255) / 256, 256>>>(W1, w1, Ln * 256, 512);
    pack_w_kernel<<<(Ln * 256 * 512 + 255) / 256, 256>>>(W2, w2, Ln * 256, 512);

    embed_kernel<<<BSn, 128>>>(loc, tdist, Wtd, btd, Wemb, bemb, x, xpk);

    for (int l = 0; l < Ln; l++) {
        bf16_gemm<2><<<dim3(12, 256), 256>>>(
            xpk, wqkv + (size_t)l * 256 * 1536, bqkv + l * 1536,
            nullptr, nullptr, qpk, kpk, vtmp, dlen, BSn, 1536, 256);
        repack_v_kernel<<<256 * 8, 256>>>(vtmp, vpk, dlen);
        flash_bf16_kernel<<<dim3(8, Bn * Hn), 256, FLASH_SMEM>>>(qpk, kpk, vpk,
                                                                 ctxpk, dlen);
        bf16_gemm<0><<<dim3(4, 256), 256>>>(
            ctxpk, wo + (size_t)l * 256 * 512, bo + l * 512,
            t1, nullptr, nullptr, nullptr, nullptr, dlen, BSn, 512, 256);
        add_ln_kernel<<<BSn, 128>>>(x, xpk, t1, ln1g + l * 512, ln1b + l * 512, dlen);
        bf16_gemm<1><<<dim3(4, 256), 256>>>(
            xpk, w1 + (size_t)l * 256 * 512, b1 + l * 512,
            nullptr, t2pk, nullptr, nullptr, nullptr, dlen, BSn, 512, 256);
        bf16_gemm<0><<<dim3(4, 256), 256>>>(
            t2pk, w2 + (size_t)l * 256 * 512, b2 + l * 512,
            t1, nullptr, nullptr, nullptr, nullptr, dlen, BSn, 512, 256);
        add_ln_kernel<<<BSn, 128>>>(x, xpk, t1, ln2g + l * 512, ln2b + l * 512, dlen);
    }

    final_logits_kernel<<<512, 256, HEAD_SMEM>>>(x, addr, poi, atype, Wa, ba,
                                                 Wout, Wcomb, dlen, lg);
    logsoftmax_kernel<<<Bn, 256>>>(lg, dlen, out);
}

// round 14
// speedup vs baseline: 1.6581x; 1.0222x over previous
#include <cuda_runtime.h>
#include <math.h>
#include <stdint.h>

#define Bn   32
#define Sn   1024
#define Dn   512
#define Hn   8
#define Ln   4
#define BSn  (Bn*Sn)

// ------------------------- scratch (device globals) -------------------------
__device__ float    g_x[(size_t)BSn * Dn];
__device__ uint32_t g_xpk[(size_t)BSn * 256];
__device__ uint32_t g_qpk[(size_t)256 * 1024 * 32];
__device__ uint32_t g_kpk[(size_t)256 * 1024 * 32];
__device__ float    g_vtmp[(size_t)256 * 1024 * 64];
__device__ uint32_t g_vpk[(size_t)256 * 512 * 64];
__device__ uint32_t g_ctxpk[(size_t)BSn * 256];
__device__ float    g_t1[(size_t)BSn * Dn];
__device__ uint32_t g_t2pk[(size_t)BSn * 256];
__device__ uint32_t g_wqkv[(size_t)Ln * 256 * 1536];
__device__ uint32_t g_wo[(size_t)Ln * 256 * 512];
__device__ uint32_t g_w1[(size_t)Ln * 256 * 512];
__device__ uint32_t g_w2[(size_t)Ln * 256 * 512];
__device__ float    g_logits[BSn];

// pack two fp32 into bf16x2: low half = first arg (even k), high = second
__device__ __forceinline__ uint32_t pk2(float lo, float hi) {
    uint32_t r;
    asm("cvt.rn.bf16x2.f32 %0, %1, %2;" : "=r"(r) : "f"(hi), "f"(lo));
    return r;
}

__device__ __forceinline__ void cpa16(uint32_t dst, const void* src) {
    asm volatile("cp.async.cg.shared.global [%0], [%1], 16;" :: "r"(dst), "l"(src));
}
#define CP_COMMIT() asm volatile("cp.async.commit_group;")
#define CP_WAIT(N)  asm volatile("cp.async.wait_group %0;" :: "n"(N))

#define MMA_BF16(C0,C1,C2,C3,A0,A1,A2,A3,B0,B1)                              \
    asm volatile(                                                            \
        "mma.sync.aligned.m16n8k16.row.col.f32.bf16.bf16.f32 "               \
        "{%0,%1,%2,%3}, {%4,%5,%6,%7}, {%8,%9}, {%0,%1,%2,%3};"              \
        : "+f"(C0), "+f"(C1), "+f"(C2), "+f"(C3)                             \
        : "r"(A0), "r"(A1), "r"(A2), "r"(A3), "r"(B0), "r"(B1))

// ============================ weight pack ===================================
__global__ void pack_w_kernel(const float* __restrict__ src,
                              uint32_t* __restrict__ dst, int KpT, int N) {
    int idx = blockIdx.x * 256 + threadIdx.x;
    if (idx >= KpT * N) return;
    int kp = idx / N;
    int n  = idx - kp * N;
    dst[idx] = pk2(src[(size_t)(2 * kp) * N + n], src[(size_t)(2 * kp + 1) * N + n]);
}

// ============================ embed =========================================
__global__ void embed_kernel(const float* __restrict__ loc,
                             const float* __restrict__ tdist,
                             const float* __restrict__ Wtd,
                             const float* __restrict__ btd,
                             const float* __restrict__ Wemb,
                             const float* __restrict__ bemb,
                             float* __restrict__ x,
                             uint32_t* __restrict__ xpk) {
    int tok = blockIdx.x;
    const float* lp = loc + (size_t)tok * 16;
    const float* tp = tdist + (size_t)tok * 8;
    float in[19];
#pragma unroll
    for (int i = 0; i < 16; i++) in[i] = lp[i];
#pragma unroll
    for (int j = 0; j < 3; j++) {
        float s = btd[j];
#pragma unroll
        for (int i = 0; i < 8; i++) s += tp[i] * Wtd[i * 3 + j];
        in[16 + j] = s;
    }
    int d = threadIdx.x * 4;
    float4 acc = *(const float4*)(bemb + d);
#pragma unroll
    for (int i = 0; i < 19; i++) {
        float4 w = *(const float4*)(Wemb + i * 512 + d);
        float s = in[i];
        acc.x += s * w.x; acc.y += s * w.y; acc.z += s * w.z; acc.w += s * w.w;
    }
    *(float4*)(x + (size_t)tok * 512 + d) = acc;
    uint2 p;
    p.x = pk2(acc.x, acc.y);
    p.y = pk2(acc.z, acc.w);
    *(uint2*)(xpk + (size_t)tok * 256 + threadIdx.x * 2) = p;
}

// ============================ bf16 tensor-core GEMM =========================
// A packed [M][Kp] bf16x2 (k-pairs), W packed [Kp][N].
// Block 128x128, chunk K=16 (8 k-pairs), 8 warps 2x4, warp tile 64x32.
// MODE 0: fp32 out. MODE 1: relu + packed bf16 out. MODE 2: QKV special.
template <int MODE>
__global__ __launch_bounds__(256)
void bf16_gemm(const uint32_t* __restrict__ Apk, const uint32_t* __restrict__ Wpk,
               const float* __restrict__ bias,
               float* __restrict__ Cf, uint32_t* __restrict__ Cpk,
               uint32_t* __restrict__ Qpk, uint32_t* __restrict__ Kpk,
               float* __restrict__ Vtmp,
               const int* __restrict__ dlen,
               int M, int N, int Kp) {
    const int bm = blockIdx.y * 128;
    if ((bm & 1023) >= dlen[bm >> 10]) return;   // whole tile invalid

    __shared__ uint32_t As[2][128 * 12];   // [m][kpair] pitch 12
    __shared__ uint32_t Ws[2][8 * 136];    // [kpair][n] pitch 136

    const int tid  = threadIdx.x;
    const int warp = tid >> 5;
    const int lane = tid & 31;
    const int wm = warp >> 2;
    const int wn = warp & 3;
    const int qid = lane >> 2;
    const int tq  = lane & 3;

    const int bn = blockIdx.x * 128;

    const int arow = tid >> 1;
    const int akp  = (tid & 1) << 2;       // 0 or 4
    const int wkp  = tid >> 5;             // 0..7
    const int wn4  = (tid & 31) << 2;      // 0..124

    const uint32_t* Ag = Apk + (size_t)(bm + arow) * Kp + akp;
    const uint32_t* Wg = Wpk + (size_t)wkp * N + bn + wn4;

    uint32_t aAd[2], aWd[2];
    {
        uint32_t a0 = (uint32_t)__cvta_generic_to_shared(&As[0][0]);
        uint32_t a1 = (uint32_t)__cvta_generic_to_shared(&As[1][0]);
        uint32_t w0 = (uint32_t)__cvta_generic_to_shared(&Ws[0][0]);
        uint32_t w1 = (uint32_t)__cvta_generic_to_shared(&Ws[1][0]);
        aAd[0] = a0 + (arow * 12 + akp) * 4;
        aAd[1] = a1 + (arow * 12 + akp) * 4;
        aWd[0] = w0 + (wkp * 136 + wn4) * 4;
        aWd[1] = w1 + (wkp * 136 + wn4) * 4;
    }

    // prologue: chunk 0
    cpa16(aAd[0], Ag);
    cpa16(aWd[0], Wg);
    CP_COMMIT();

    float acc[4][4][4];
#pragma unroll
    for (int i = 0; i < 4; i++)
#pragma unroll
        for (int j = 0; j < 4; j++)
#pragma unroll
            for (int c = 0; c < 4; c++) acc[i][j][c] = 0.f;

    const int nck = Kp >> 3;
    for (int kc = 0; kc < nck; kc++) {
        const int s = kc & 1;
        if (kc + 1 < nck) {
            cpa16(aAd[s ^ 1], Ag + (kc + 1) * 8);
            cpa16(aWd[s ^ 1], Wg + (size_t)(kc + 1) * 8 * N);
            CP_COMMIT();
            CP_WAIT(1);
        } else {
            CP_WAIT(0);
        }
        __syncthreads();

        const uint32_t* as_ = As[s];
        const uint32_t* ws_ = Ws[s];
        unsigned a[4][4], b[4][2];
#pragma unroll
        for (int am = 0; am < 4; am++) {
            int m = wm * 64 + am * 16;
            a[am][0] = as_[(m + qid) * 12 + tq];
            a[am][1] = as_[(m + qid + 8) * 12 + tq];
            a[am][2] = as_[(m + qid) * 12 + tq + 4];
            a[am][3] = as_[(m + qid + 8) * 12 + tq + 4];
        }
#pragma unroll
        for (int an = 0; an < 4; an++) {
            int n0 = wn * 32 + an * 8;
            b[an][0] = ws_[tq * 136 + n0 + qid];
            b[an][1] = ws_[(tq + 4) * 136 + n0 + qid];
        }
#pragma unroll
        for (int am = 0; am < 4; am++)
#pragma unroll
            for (int an = 0; an < 4; an++)
                MMA_BF16(acc[am][an][0], acc[am][an][1],
                         acc[am][an][2], acc[am][an][3],
                         a[am][0], a[am][1], a[am][2], a[am][3],
                         b[an][0], b[an][1]);
        __syncthreads();
    }

    // epilogue
#pragma unroll
    for (int am = 0; am < 4; am++) {
        int r0 = bm + wm * 64 + am * 16 + qid;
#pragma unroll
        for (int an = 0; an < 4; an++) {
            int col = bn + wn * 32 + an * 8 + 2 * tq;
            float b0 = bias[col], b1 = bias[col + 1];
            float v0 = acc[am][an][0] + b0;
            float v1 = acc[am][an][1] + b1;
            float v2 = acc[am][an][2] + b0;
            float v3 = acc[am][an][3] + b1;
            if (MODE == 0) {
                *(float2*)(Cf + (size_t)r0 * N + col)       = make_float2(v0, v1);
                *(float2*)(Cf + (size_t)(r0 + 8) * N + col) = make_float2(v2, v3);
            } else if (MODE == 1) {
                v0 = fmaxf(v0, 0.f); v1 = fmaxf(v1, 0.f);
                v2 = fmaxf(v2, 0.f); v3 = fmaxf(v3, 0.f);
                Cpk[(size_t)r0 * (N >> 1) + (col >> 1)]       = pk2(v0, v1);
                Cpk[(size_t)(r0 + 8) * (N >> 1) + (col >> 1)] = pk2(v2, v3);
            } else {
                int bb = r0 >> 10;
                int sr = r0 & 1023;
                int h  = (col >> 6) & 7;
                size_t bh = (size_t)(bb * 8 + h);
                if (col < 512) {
                    v0 *= 0.125f; v1 *= 0.125f; v2 *= 0.125f; v3 *= 0.125f;
                    size_t base = (bh * 1024 + sr) * 32 + ((col & 63) >> 1);
                    Qpk[base]            = pk2(v0, v1);
                    Qpk[base + 8 * 32]   = pk2(v2, v3);
                } else if (col < 1024) {
                    size_t base = (bh * 1024 + sr) * 32 + ((col & 63) >> 1);
                    Kpk[base]            = pk2(v0, v1);
                    Kpk[base + 8 * 32]   = pk2(v2, v3);
                } else {
                    size_t base = (bh * 1024 + sr) * 64 + (col & 63);
                    *(float2*)(Vtmp + base)            = make_float2(v0, v1);
                    *(float2*)(Vtmp + base + 8 * 64)   = make_float2(v2, v3);
                }
            }
        }
    }
}

// ============================ V repack (key-pair packing) ===================
__global__ __launch_bounds__(256)
void repack_v_kernel(const float* __restrict__ Vtmp, uint32_t* __restrict__ Vpk,
                     const int* __restrict__ dlen) {
    int bh  = blockIdx.x >> 3;
    int kp0 = (blockIdx.x & 7) * 64;
    if (kp0 * 2 >= dlen[bh >> 3]) return;
    const float* src = Vtmp + (size_t)bh * 1024 * 64;
    uint32_t* dst = Vpk + ((size_t)bh * 512 + kp0) * 64;
    for (int i = threadIdx.x; i < 64 * 64; i += 256) {
        int kpl = i >> 6;
        int d   = i & 63;
        int key0 = 2 * (kp0 + kpl);
        dst[(size_t)kpl * 64 + d] = pk2(src[(size_t)key0 * 64 + d],
                                        src[(size_t)(key0 + 1) * 64 + d]);
    }
}

// ============================ flash attention (bf16 mma, register P) ========
#define QP  36
#define KPT 36
#define VPT 72
#define KTILE (64 * KPT)
#define VTILE (32 * VPT)
#define FSTG (KTILE + VTILE)
#define QTILE (128 * QP)
#define FLASH_SMEM ((2 * FSTG + QTILE) * 4)

__global__ __launch_bounds__(256)
void flash_bf16_kernel(const uint32_t* __restrict__ Qpk,
                       const uint32_t* __restrict__ Kpk,
                       const uint32_t* __restrict__ Vpk,
                       uint32_t* __restrict__ ctxpk,
                       const int* __restrict__ dlen) {
    extern __shared__ uint32_t smu[];

    const int qt = blockIdx.x;
    const int bh = blockIdx.y;
    const int b  = bh >> 3;
    const int len = dlen[b];
    if (qt * 128 >= len) return;
    const int nk = (len + 63) >> 6;

    const int tid = threadIdx.x;
    const int warp = tid >> 5;
    const int lane = tid & 31;
    const int qid = lane >> 2;
    const int tq  = lane & 3;
    const int m0  = warp * 16;

    const uint32_t* Qg = Qpk + ((size_t)bh * 1024 + qt * 128) * 32;
    const uint32_t* Kg = Kpk + (size_t)bh * 1024 * 32;
    const uint32_t* Vg = Vpk + (size_t)bh * 512 * 64;

    uint32_t* Qs = smu + 2 * FSTG;
    uint32_t smbase = (uint32_t)__cvta_generic_to_shared(smu);
    uint32_t qbase  = smbase + 2 * FSTG * 4;

    // group 1: Q tile
#pragma unroll
    for (int u = 0; u < 4; u++) {
        int f = tid + u * 256;
        int r = f >> 3, c4 = (f & 7) << 2;
        cpa16(qbase + (r * QP + c4) * 4, Qg + (size_t)r * 32 + c4);
    }
    CP_COMMIT();
    // group 2: K/V tile 0
    {
        uint32_t kd = smbase, vd = smbase + KTILE * 4;
#pragma unroll
        for (int u = 0; u < 2; u++) {
            int f = tid + u * 256;
            int rk = f >> 3, ck = (f & 7) << 2;
            cpa16(kd + (rk * KPT + ck) * 4, Kg + (size_t)rk * 32 + ck);
            int rv = f >> 4, cv = (f & 15) << 2;
            cpa16(vd + (rv * VPT + cv) * 4, Vg + (size_t)rv * 64 + cv);
        }
        CP_COMMIT();
    }
    CP_WAIT(1);
    __syncthreads();

    // Q fragments: 4 d-chunks of k16
    unsigned aq[4][4];
#pragma unroll
    for (int s = 0; s < 4; s++) {
        aq[s][0] = Qs[(m0 + qid) * QP + s * 8 + tq];
        aq[s][1] = Qs[(m0 + qid + 8) * QP + s * 8 + tq];
        aq[s][2] = Qs[(m0 + qid) * QP + s * 8 + tq + 4];
        aq[s][3] = Qs[(m0 + qid + 8) * QP + s * 8 + tq + 4];
    }

    float mr0 = -1e30f, mr1 = -1e30f, lr0 = 0.f, lr1 = 0.f;
    float O[8][4];
#pragma unroll
    for (int n = 0; n < 8; n++)
#pragma unroll
        for (int c = 0; c < 4; c++) O[n][c] = 0.f;

    for (int kt = 0; kt < nk; kt++) {
        __syncthreads();
        if (kt + 1 < nk) {
            uint32_t sb = smbase + ((kt + 1) & 1) * FSTG * 4;
            uint32_t kd = sb, vd = sb + KTILE * 4;
            const uint32_t* kg = Kg + (size_t)(kt + 1) * 64 * 32;
            const uint32_t* vg = Vg + (size_t)(kt + 1) * 32 * 64;
#pragma unroll
            for (int u = 0; u < 2; u++) {
                int f = tid + u * 256;
                int rk = f >> 3, ck = (f & 7) << 2;
                cpa16(kd + (rk * KPT + ck) * 4, kg + (size_t)rk * 32 + ck);
                int rv = f >> 4, cv = (f & 15) << 2;
                cpa16(vd + (rv * VPT + cv) * 4, vg + (size_t)rv * 64 + cv);
            }
            CP_COMMIT();
            CP_WAIT(1);
        } else {
            CP_WAIT(0);
        }
        __syncthreads();

        const uint32_t* Ks = smu + (kt & 1) * FSTG;
        const uint32_t* Vs = Ks + KTILE;

        // ---- S = Q @ K^T (Q pre-scaled) ----
        float c[8][4];
#pragma unroll
        for (int n = 0; n < 8; n++)
#pragma unroll
            for (int j = 0; j < 4; j++) c[n][j] = 0.f;

#pragma unroll
        for (int s = 0; s < 4; s++) {
#pragma unroll
            for (int n = 0; n < 8; n++) {
                unsigned b0 = Ks[(n * 8 + qid) * KPT + s * 8 + tq];
                unsigned b1 = Ks[(n * 8 + qid) * KPT + s * 8 + tq + 4];
                MMA_BF16(c[n][0], c[n][1], c[n][2], c[n][3],
                         aq[s][0], aq[s][1], aq[s][2], aq[s][3], b0, b1);
            }
        }

        // ---- mask + online softmax (mask ASSIGNS; stale-K can't leak) ----
        const int cb = kt * 64 + 2 * tq;
        float mx0 = -1e30f, mx1 = -1e30f;
#pragma unroll
        for (int n = 0; n < 8; n++) {
            int c0 = cb + n * 8, c1 = c0 + 1;
            if (c0 >= len) { c[n][0] = -1e30f; c[n][2] = -1e30f; }
            if (c1 >= len) { c[n][1] = -1e30f; c[n][3] = -1e30f; }
            mx0 = fmaxf(mx0, fmaxf(c[n][0], c[n][1]));
            mx1 = fmaxf(mx1, fmaxf(c[n][2], c[n][3]));
        }
        mx0 = fmaxf(mx0, __shfl_xor_sync(0xffffffffu, mx0, 1));
        mx0 = fmaxf(mx0, __shfl_xor_sync(0xffffffffu, mx0, 2));
        mx1 = fmaxf(mx1, __shfl_xor_sync(0xffffffffu, mx1, 1));
        mx1 = fmaxf(mx1, __shfl_xor_sync(0xffffffffu, mx1, 2));

        float mn0 = fmaxf(mr0, mx0), mn1 = fmaxf(mr1, mx1);
        float al0 = __expf(mr0 - mn0), al1 = __expf(mr1 - mn1);
        float rs0 = 0.f, rs1 = 0.f;
#pragma unroll
        for (int n = 0; n < 8; n++) {
            c[n][0] = __expf(c[n][0] - mn0);
            c[n][1] = __expf(c[n][1] - mn0);
            c[n][2] = __expf(c[n][2] - mn1);
            c[n][3] = __expf(c[n][3] - mn1);
            rs0 += c[n][0] + c[n][1];
            rs1 += c[n][2] + c[n][3];
        }
        rs0 += __shfl_xor_sync(0xffffffffu, rs0, 1);
        rs0 += __shfl_xor_sync(0xffffffffu, rs0, 2);
        rs1 += __shfl_xor_sync(0xffffffffu, rs1, 1);
        rs1 += __shfl_xor_sync(0xffffffffu, rs1, 2);
        lr0 = lr0 * al0 + rs0;
        lr1 = lr1 * al1 + rs1;
        mr0 = mn0; mr1 = mn1;
#pragma unroll
        for (int n = 0; n < 8; n++) {
            O[n][0] *= al0; O[n][1] *= al0;
            O[n][2] *= al1; O[n][3] *= al1;
        }

        // ---- O += P @ V, P repacked C-frag -> A-frag entirely in registers:
        //  a0 = P[qid][16s+2tq,+1]   = pk2(c[2s][0],  c[2s][1])
        //  a1 = P[qid+8][16s+2tq,+1] = pk2(c[2s][2],  c[2s][3])
        //  a2 = P[qid][16s+8+2tq,+1] = pk2(c[2s+1][0],c[2s+1][1])
        //  a3 = P[qid+8][16s+8+2tq,] = pk2(c[2s+1][2],c[2s+1][3])
#pragma unroll
        for (int s = 0; s < 4; s++) {
            unsigned ap0 = pk2(c[2 * s][0],     c[2 * s][1]);
            unsigned ap1 = pk2(c[2 * s][2],     c[2 * s][3]);
            unsigned ap2 = pk2(c[2 * s + 1][0], c[2 * s + 1][1]);
            unsigned ap3 = pk2(c[2 * s + 1][2], c[2 * s + 1][3]);
#pragma unroll
            for (int n = 0; n < 8; n++) {
                unsigned b0 = Vs[(s * 8 + tq) * VPT + n * 8 + qid];
                unsigned b1 = Vs[(s * 8 + tq + 4) * VPT + n * 8 + qid];
                MMA_BF16(O[n][0], O[n][1], O[n][2], O[n][3],
                         ap0, ap1, ap2, ap3, b0, b1);
            }
        }
    }

    // ---- epilogue: packed ctx ----
    float inv0 = 1.f / lr0, inv1 = 1.f / lr1;
    int h = bh & 7;
    size_t row0 = (size_t)(b * Sn + qt * 128 + m0 + qid);
#pragma unroll
    for (int n = 0; n < 8; n++) {
        int dp = h * 32 + 4 * n + tq;
        ctxpk[row0 * 256 + dp]       = pk2(O[n][0] * inv0, O[n][1] * inv0);
        ctxpk[(row0 + 8) * 256 + dp] = pk2(O[n][2] * inv1, O[n][3] * inv1);
    }
}

// ============================ add + layernorm ===============================
__device__ __forceinline__ float blk_sum_128(float v, float* red) {
#pragma unroll
    for (int o = 16; o; o >>= 1) v += __shfl_xor_sync(0xffffffffu, v, o);
    __syncthreads();
    if ((threadIdx.x & 31) == 0) red[threadIdx.x >> 5] = v;
    __syncthreads();
    return red[0] + red[1] + red[2] + red[3];
}

__global__ __launch_bounds__(128)
void add_ln_kernel(float* __restrict__ x, uint32_t* __restrict__ xpk,
                   const float* __restrict__ hh,
                   const float* __restrict__ g, const float* __restrict__ be,
                   const int* __restrict__ dlen) {
    int row = blockIdx.x;
    if ((row & 1023) >= dlen[row >> 10]) return;
    __shared__ float red[4];
    int t = threadIdx.x;
    size_t off = (size_t)row * 512 + t * 4;
    float4 xv = *(float4*)(x + off);
    float4 hv = *(const float4*)(hh + off);
    float v0 = xv.x + hv.x, v1 = xv.y + hv.y, v2 = xv.z + hv.z, v3 = xv.w + hv.w;
    float mean = blk_sum_128(v0 + v1 + v2 + v3, red) * (1.f / 512.f);
    float d0 = v0 - mean, d1 = v1 - mean, d2 = v2 - mean, d3 = v3 - mean;
    float var = blk_sum_128(d0 * d0 + d1 * d1 + d2 * d2 + d3 * d3, red) * (1.f / 512.f);
    float rstd = rsqrtf(var + 1e-5f);
    float4 gv = *(const float4*)(g + t * 4);
    float4 bv = *(const float4*)(be + t * 4);
    float4 o;
    o.x = d0 * rstd * gv.x + bv.x;
    o.y = d1 * rstd * gv.y + bv.y;
    o.z = d2 * rstd * gv.z + bv.z;
    o.w = d3 * rstd * gv.w + bv.w;
    *(float4*)(x + off) = o;
    uint2 p;
    p.x = pk2(o.x, o.y);
    p.y = pk2(o.z, o.w);
    *(uint2*)(xpk + (size_t)row * 256 + t * 2) = p;
}

// ============================ final head ====================================
#define HEAD_SMEM (512 * 32 * 4)

__global__ __launch_bounds__(256)
void final_logits_kernel(const float* __restrict__ x, const float* __restrict__ addr,
                         const float* __restrict__ poi, const int* __restrict__ atype,
                         const float* __restrict__ Wa, const float* __restrict__ ba,
                         const float* __restrict__ Wout, const float* __restrict__ Wcomb,
                         const int* __restrict__ dlen, float* __restrict__ logits) {
    extern __shared__ float ws[];
    for (int i = threadIdx.x; i < 512 * 32; i += 256) ws[i] = Wout[i];
    __syncthreads();

    const int warp = threadIdx.x >> 5;
    const int lane = threadIdx.x & 31;
    const float wc = Wcomb[lane];

    for (int tok = blockIdx.x * 8 + warp; tok < BSn; tok += gridDim.x * 8) {
        int b = tok >> 10;
        int s = tok & 1023;
        if (s >= dlen[b]) continue;
        int t = atype[b];
        float aj = ba[lane]
                 + addr[b]        * Wa[lane]
                 + poi[t * 3 + 0] * Wa[32 + lane]
                 + poi[t * 3 + 1] * Wa[64 + lane]
                 + poi[t * 3 + 2] * Wa[96 + lane];
        const float* xr = x + (size_t)tok * 512;
        float acc = 0.f;
        for (int d0 = 0; d0 < 512; d0 += 32) {
            float xv = xr[d0 + lane];
#pragma unroll
            for (int j = 0; j < 32; j++)
                acc += __shfl_sync(0xffffffffu, xv, j) * ws[(d0 + j) * 32 + lane];
        }
        float tv = tanhf(acc + aj) * wc;
#pragma unroll
        for (int o = 16; o; o >>= 1) tv += __shfl_xor_sync(0xffffffffu, tv, o);
        if (lane == 0) logits[tok] = tv;
    }
}

__global__ __launch_bounds__(256)
void logsoftmax_kernel(const float* __restrict__ logits, const int* __restrict__ dlen,
                       float* __restrict__ out) {
    __shared__ float red[8];
    int b = blockIdx.x;
    int len = dlen[b];
    const float* lg = logits + (size_t)b * Sn;
    float mx = -1e30f;
    for (int s = threadIdx.x; s < len; s += 256) mx = fmaxf(mx, lg[s]);
#pragma unroll
    for (int o = 16; o; o >>= 1) mx = fmaxf(mx, __shfl_xor_sync(0xffffffffu, mx, o));
    if ((threadIdx.x & 31) == 0) red[threadIdx.x >> 5] = mx;
    __syncthreads();
    mx = red[0];
#pragma unroll
    for (int w = 1; w < 8; w++) mx = fmaxf(mx, red[w]);
    __syncthreads();
    float sum = 0.f;
    for (int s = threadIdx.x; s < len; s += 256) sum += expf(lg[s] - mx);
#pragma unroll
    for (int o = 16; o; o >>= 1) sum += __shfl_xor_sync(0xffffffffu, sum, o);
    if ((threadIdx.x & 31) == 0) red[threadIdx.x >> 5] = sum;
    __syncthreads();
    sum = red[0] + red[1] + red[2] + red[3] + red[4] + red[5] + red[6] + red[7];
    float lse = logf(sum) + mx;
    for (int s = threadIdx.x; s < Sn; s += 256)
        out[(size_t)b * Sn + s] = (s < len) ? (lg[s] - lse) : 0.f;
}

// ============================ launch ========================================
extern "C" void kernel_launch(void* const* d_in, const int* in_sizes, int n_in,
                              void* d_out, int out_size) {
    const float* addr  = (const float*)d_in[0];
    const float* loc   = (const float*)d_in[1];
    const float* tdist = (const float*)d_in[2];
    const float* Wtd   = (const float*)d_in[3];
    const float* btd   = (const float*)d_in[4];
    const float* Wemb  = (const float*)d_in[5];
    const float* bemb  = (const float*)d_in[6];
    const float* Wqkv  = (const float*)d_in[7];
    const float* bqkv  = (const float*)d_in[8];
    const float* Wo    = (const float*)d_in[9];
    const float* bo    = (const float*)d_in[10];
    const float* ln1g  = (const float*)d_in[11];
    const float* ln1b  = (const float*)d_in[12];
    const float* W1    = (const float*)d_in[13];
    const float* b1    = (const float*)d_in[14];
    const float* W2    = (const float*)d_in[15];
    const float* b2    = (const float*)d_in[16];
    const float* ln2g  = (const float*)d_in[17];
    const float* ln2b  = (const float*)d_in[18];
    const float* poi   = (const float*)d_in[19];
    const float* Wa    = (const float*)d_in[20];
    const float* ba    = (const float*)d_in[21];
    const float* Wout  = (const float*)d_in[22];
    const float* Wcomb = (const float*)d_in[23];
    const int*   atype = (const int*)d_in[24];
    const int*   dlen  = (const int*)d_in[25];
    float* out = (float*)d_out;

    float *x, *t1, *vtmp, *lg;
    uint32_t *xpk, *qpk, *kpk, *vpk, *ctxpk, *t2pk, *wqkv, *wo, *w1, *w2;
    cudaGetSymbolAddress((void**)&x,     g_x);
    cudaGetSymbolAddress((void**)&xpk,   g_xpk);
    cudaGetSymbolAddress((void**)&qpk,   g_qpk);
    cudaGetSymbolAddress((void**)&kpk,   g_kpk);
    cudaGetSymbolAddress((void**)&vtmp,  g_vtmp);
    cudaGetSymbolAddress((void**)&vpk,   g_vpk);
    cudaGetSymbolAddress((void**)&ctxpk, g_ctxpk);
    cudaGetSymbolAddress((void**)&t1,    g_t1);
    cudaGetSymbolAddress((void**)&t2pk,  g_t2pk);
    cudaGetSymbolAddress((void**)&wqkv,  g_wqkv);
    cudaGetSymbolAddress((void**)&wo,    g_wo);
    cudaGetSymbolAddress((void**)&w1,    g_w1);
    cudaGetSymbolAddress((void**)&w2,    g_w2);
    cudaGetSymbolAddress((void**)&lg,    g_logits);

    cudaFuncSetAttribute(flash_bf16_kernel,
                         cudaFuncAttributeMaxDynamicSharedMemorySize, FLASH_SMEM);
    cudaFuncSetAttribute(final_logits_kernel,
                         cudaFuncAttributeMaxDynamicSharedMemorySize, HEAD_SMEM);

    // pack all weights (bf16x2 along K)
    pack_w_kernel<<<(Ln * 256 * 1536 + 255) / 256, 256>>>(Wqkv, wqkv, Ln * 256, 1536);
    pack_w_kernel<<<(Ln * 256 * 512 + 255) / 256, 256>>>(Wo, wo, Ln * 256, 512);
    pack_w_kernel<<<(Ln * 256 * 512 + 255) / 256, 256>>>(W1, w1, Ln * 256, 512);
    pack_w_kernel<<<(Ln * 256 * 512 + 255) / 256, 256>>>(W2, w2, Ln * 256, 512);

    embed_kernel<<<BSn, 128>>>(loc, tdist, Wtd, btd, Wemb, bemb, x, xpk);

    for (int l = 0; l < Ln; l++) {
        bf16_gemm<2><<<dim3(12, 256), 256>>>(
            xpk, wqkv + (size_t)l * 256 * 1536, bqkv + l * 1536,
            nullptr, nullptr, qpk, kpk, vtmp, dlen, BSn, 1536, 256);
        repack_v_kernel<<<256 * 8, 256>>>(vtmp, vpk, dlen);
        flash_bf16_kernel<<<dim3(8, Bn * Hn), 256, FLASH_SMEM>>>(qpk, kpk, vpk,
                                                                 ctxpk, dlen);
        bf16_gemm<0><<<dim3(4, 256), 256>>>(
            ctxpk, wo + (size_t)l * 256 * 512, bo + l * 512,
            t1, nullptr, nullptr, nullptr, nullptr, dlen, BSn, 512, 256);
        add_ln_kernel<<<BSn, 128>>>(x, xpk, t1, ln1g + l * 512, ln1b + l * 512, dlen);
        bf16_gemm<1><<<dim3(4, 256), 256>>>(
            xpk, w1 + (size_t)l * 256 * 512, b1 + l * 512,
            nullptr, t2pk, nullptr, nullptr, nullptr, dlen, BSn, 512, 256);
        bf16_gemm<0><<<dim3(4, 256), 256>>>(
            t2pk, w2 + (size_t)l * 256 * 512, b2 + l * 512,
            t1, nullptr, nullptr, nullptr, nullptr, dlen, BSn, 512, 256);
        add_ln_kernel<<<BSn, 128>>>(x, xpk, t1, ln2g + l * 512, ln2b + l * 512, dlen);
    }

    final_logits_kernel<<<512, 256, HEAD_SMEM>>>(x, addr, poi, atype, Wa, ba,
                                                 Wout, Wcomb, dlen, lg);
    logsoftmax_kernel<<<Bn, 256>>>(lg, dlen, out);
}

// round 16
// speedup vs baseline: 1.6919x; 1.0204x over previous
#include <cuda_runtime.h>
#include <math.h>
#include <stdint.h>

#define Bn   32
#define Sn   1024
#define Dn   512
#define Hn   8
#define Ln   4
#define BSn  (Bn*Sn)

// ------------------------- scratch (device globals) -------------------------
__device__ float    g_x[(size_t)BSn * Dn];
__device__ uint32_t g_xpk[(size_t)BSn * 256];
__device__ uint32_t g_qpk[(size_t)256 * 1024 * 32];
__device__ uint32_t g_kpk[(size_t)256 * 1024 * 32];
__device__ uint32_t g_vpk[(size_t)256 * 512 * 64];
__device__ uint32_t g_ctxpk[(size_t)BSn * 256];
__device__ float    g_t1[(size_t)BSn * Dn];
__device__ uint32_t g_t2pk[(size_t)BSn * 256];
__device__ uint32_t g_wqkv[(size_t)Ln * 256 * 1536];
__device__ uint32_t g_wo[(size_t)Ln * 256 * 512];
__device__ uint32_t g_w1[(size_t)Ln * 256 * 512];
__device__ uint32_t g_w2[(size_t)Ln * 256 * 512];
__device__ float    g_logits[BSn];

// pack two fp32 into bf16x2: low half = first arg (even k), high = second
__device__ __forceinline__ uint32_t pk2(float lo, float hi) {
    uint32_t r;
    asm("cvt.rn.bf16x2.f32 %0, %1, %2;" : "=r"(r) : "f"(hi), "f"(lo));
    return r;
}

__device__ __forceinline__ void cpa16(uint32_t dst, const void* src) {
    asm volatile("cp.async.cg.shared.global [%0], [%1], 16;" :: "r"(dst), "l"(src));
}
#define CP_COMMIT() asm volatile("cp.async.commit_group;")
#define CP_WAIT(N)  asm volatile("cp.async.wait_group %0;" :: "n"(N))

#define MMA_BF16(C0,C1,C2,C3,A0,A1,A2,A3,B0,B1)                              \
    asm volatile(                                                            \
        "mma.sync.aligned.m16n8k16.row.col.f32.bf16.bf16.f32 "               \
        "{%0,%1,%2,%3}, {%4,%5,%6,%7}, {%8,%9}, {%0,%1,%2,%3};"              \
        : "+f"(C0), "+f"(C1), "+f"(C2), "+f"(C3)                             \
        : "r"(A0), "r"(A1), "r"(A2), "r"(A3), "r"(B0), "r"(B1))

// ============================ weight pack ===================================
__global__ void pack_w_kernel(const float* __restrict__ src,
                              uint32_t* __restrict__ dst, int KpT, int N) {
    int idx = blockIdx.x * 256 + threadIdx.x;
    if (idx >= KpT * N) return;
    int kp = idx / N;
    int n  = idx - kp * N;
    dst[idx] = pk2(src[(size_t)(2 * kp) * N + n], src[(size_t)(2 * kp + 1) * N + n]);
}

// ============================ embed =========================================
__global__ void embed_kernel(const float* __restrict__ loc,
                             const float* __restrict__ tdist,
                             const float* __restrict__ Wtd,
                             const float* __restrict__ btd,
                             const float* __restrict__ Wemb,
                             const float* __restrict__ bemb,
                             float* __restrict__ x,
                             uint32_t* __restrict__ xpk) {
    int tok = blockIdx.x;
    const float* lp = loc + (size_t)tok * 16;
    const float* tp = tdist + (size_t)tok * 8;
    float in[19];
#pragma unroll
    for (int i = 0; i < 16; i++) in[i] = lp[i];
#pragma unroll
    for (int j = 0; j < 3; j++) {
        float s = btd[j];
#pragma unroll
        for (int i = 0; i < 8; i++) s += tp[i] * Wtd[i * 3 + j];
        in[16 + j] = s;
    }
    int d = threadIdx.x * 4;
    float4 acc = *(const float4*)(bemb + d);
#pragma unroll
    for (int i = 0; i < 19; i++) {
        float4 w = *(const float4*)(Wemb + i * 512 + d);
        float s = in[i];
        acc.x += s * w.x; acc.y += s * w.y; acc.z += s * w.z; acc.w += s * w.w;
    }
    *(float4*)(x + (size_t)tok * 512 + d) = acc;
    uint2 p;
    p.x = pk2(acc.x, acc.y);
    p.y = pk2(acc.z, acc.w);
    *(uint2*)(xpk + (size_t)tok * 256 + threadIdx.x * 2) = p;
}

// ============================ bf16 tensor-core GEMM =========================
// A packed [M][Kp] bf16x2 (k-pairs), W packed [Kp][N].
// Block 128x128, chunk K=16 (8 k-pairs), 8 warps 2x4, warp tile 64x32.
// MODE 0: fp32 out. MODE 1: relu + packed bf16 out.
// MODE 2: QKV special — Q/K packed along d; V key-pair packed DIRECTLY via
//         shfl butterfly (lane^4 swaps qid parity -> adjacent seq rows).
template <int MODE>
__global__ __launch_bounds__(256)
void bf16_gemm(const uint32_t* __restrict__ Apk, const uint32_t* __restrict__ Wpk,
               const float* __restrict__ bias,
               float* __restrict__ Cf, uint32_t* __restrict__ Cpk,
               uint32_t* __restrict__ Qpk, uint32_t* __restrict__ Kpk,
               uint32_t* __restrict__ Vpk,
               const int* __restrict__ dlen,
               int M, int N, int Kp) {
    const int bm = blockIdx.y * 128;
    if ((bm & 1023) >= dlen[bm >> 10]) return;   // whole tile invalid

    __shared__ uint32_t As[2][128 * 12];   // [m][kpair] pitch 12
    __shared__ uint32_t Ws[2][8 * 136];    // [kpair][n] pitch 136

    const int tid  = threadIdx.x;
    const int warp = tid >> 5;
    const int lane = tid & 31;
    const int wm = warp >> 2;
    const int wn = warp & 3;
    const int qid = lane >> 2;
    const int tq  = lane & 3;

    const int bn = blockIdx.x * 128;

    const int arow = tid >> 1;
    const int akp  = (tid & 1) << 2;       // 0 or 4
    const int wkp  = tid >> 5;             // 0..7
    const int wn4  = (tid & 31) << 2;      // 0..124

    const uint32_t* Ag = Apk + (size_t)(bm + arow) * Kp + akp;
    const uint32_t* Wg = Wpk + (size_t)wkp * N + bn + wn4;

    uint32_t aAd[2], aWd[2];
    {
        uint32_t a0 = (uint32_t)__cvta_generic_to_shared(&As[0][0]);
        uint32_t a1 = (uint32_t)__cvta_generic_to_shared(&As[1][0]);
        uint32_t w0 = (uint32_t)__cvta_generic_to_shared(&Ws[0][0]);
        uint32_t w1 = (uint32_t)__cvta_generic_to_shared(&Ws[1][0]);
        aAd[0] = a0 + (arow * 12 + akp) * 4;
        aAd[1] = a1 + (arow * 12 + akp) * 4;
        aWd[0] = w0 + (wkp * 136 + wn4) * 4;
        aWd[1] = w1 + (wkp * 136 + wn4) * 4;
    }

    // prologue: chunk 0
    cpa16(aAd[0], Ag);
    cpa16(aWd[0], Wg);
    CP_COMMIT();

    float acc[4][4][4];
#pragma unroll
    for (int i = 0; i < 4; i++)
#pragma unroll
        for (int j = 0; j < 4; j++)
#pragma unroll
            for (int c = 0; c < 4; c++) acc[i][j][c] = 0.f;

    const int nck = Kp >> 3;
    for (int kc = 0; kc < nck; kc++) {
        const int s = kc & 1;
        if (kc + 1 < nck) {
            cpa16(aAd[s ^ 1], Ag + (kc + 1) * 8);
            cpa16(aWd[s ^ 1], Wg + (size_t)(kc + 1) * 8 * N);
            CP_COMMIT();
            CP_WAIT(1);
        } else {
            CP_WAIT(0);
        }
        __syncthreads();

        const uint32_t* as_ = As[s];
        const uint32_t* ws_ = Ws[s];
        unsigned a[4][4], b[4][2];
#pragma unroll
        for (int am = 0; am < 4; am++) {
            int m = wm * 64 + am * 16;
            a[am][0] = as_[(m + qid) * 12 + tq];
            a[am][1] = as_[(m + qid + 8) * 12 + tq];
            a[am][2] = as_[(m + qid) * 12 + tq + 4];
            a[am][3] = as_[(m + qid + 8) * 12 + tq + 4];
        }
#pragma unroll
        for (int an = 0; an < 4; an++) {
            int n0 = wn * 32 + an * 8;
            b[an][0] = ws_[tq * 136 + n0 + qid];
            b[an][1] = ws_[(tq + 4) * 136 + n0 + qid];
        }
#pragma unroll
        for (int am = 0; am < 4; am++)
#pragma unroll
            for (int an = 0; an < 4; an++)
                MMA_BF16(acc[am][an][0], acc[am][an][1],
                         acc[am][an][2], acc[am][an][3],
                         a[am][0], a[am][1], a[am][2], a[am][3],
                         b[an][0], b[an][1]);
        __syncthreads();
    }

    // epilogue
#pragma unroll
    for (int am = 0; am < 4; am++) {
        int r0 = bm + wm * 64 + am * 16 + qid;
#pragma unroll
        for (int an = 0; an < 4; an++) {
            int col = bn + wn * 32 + an * 8 + 2 * tq;
            float b0 = bias[col], b1 = bias[col + 1];
            float v0 = acc[am][an][0] + b0;
            float v1 = acc[am][an][1] + b1;
            float v2 = acc[am][an][2] + b0;
            float v3 = acc[am][an][3] + b1;
            if (MODE == 0) {
                *(float2*)(Cf + (size_t)r0 * N + col)       = make_float2(v0, v1);
                *(float2*)(Cf + (size_t)(r0 + 8) * N + col) = make_float2(v2, v3);
            } else if (MODE == 1) {
                v0 = fmaxf(v0, 0.f); v1 = fmaxf(v1, 0.f);
                v2 = fmaxf(v2, 0.f); v3 = fmaxf(v3, 0.f);
                Cpk[(size_t)r0 * (N >> 1) + (col >> 1)]       = pk2(v0, v1);
                Cpk[(size_t)(r0 + 8) * (N >> 1) + (col >> 1)] = pk2(v2, v3);
            } else {
                int bb = r0 >> 10;
                int sr = r0 & 1023;
                int h  = (col >> 6) & 7;
                size_t bh = (size_t)(bb * 8 + h);
                if (col < 512) {
                    v0 *= 0.125f; v1 *= 0.125f; v2 *= 0.125f; v3 *= 0.125f;
                    size_t base = (bh * 1024 + sr) * 32 + ((col & 63) >> 1);
                    Qpk[base]            = pk2(v0, v1);
                    Qpk[base + 8 * 32]   = pk2(v2, v3);
                } else if (col < 1024) {
                    size_t base = (bh * 1024 + sr) * 32 + ((col & 63) >> 1);
                    Kpk[base]            = pk2(v0, v1);
                    Kpk[base + 8 * 32]   = pk2(v2, v3);
                } else {
                    // V: key-pair pack via shfl. Partner row (qid^1) lives in
                    // lane^4. Even-qid lanes pack rows (r0, r0+1) and
                    // (r0+8, r0+9) -> key pairs sr/2 and sr/2+4.
                    float p0 = __shfl_xor_sync(0xffffffffu, v0, 4);
                    float p1 = __shfl_xor_sync(0xffffffffu, v1, 4);
                    float p2 = __shfl_xor_sync(0xffffffffu, v2, 4);
                    float p3 = __shfl_xor_sync(0xffffffffu, v3, 4);
                    if ((qid & 1) == 0) {
                        int d = col & 63;
                        size_t base = (bh * 512 + (sr >> 1)) * 64 + d;
                        Vpk[base]              = pk2(v0, p0);
                        Vpk[base + 1]          = pk2(v1, p1);
                        Vpk[base + 4 * 64]     = pk2(v2, p2);
                        Vpk[base + 4 * 64 + 1] = pk2(v3, p3);
                    }
                }
            }
        }
    }
}

// ============================ flash attention (bf16 mma, register P) ========
#define QP  36
#define KPT 36
#define VPT 72
#define KTILE (64 * KPT)
#define VTILE (32 * VPT)
#define FSTG (KTILE + VTILE)
#define QTILE (128 * QP)
#define FLASH_SMEM ((2 * FSTG + QTILE) * 4)

__global__ __launch_bounds__(256)
void flash_bf16_kernel(const uint32_t* __restrict__ Qpk,
                       const uint32_t* __restrict__ Kpk,
                       const uint32_t* __restrict__ Vpk,
                       uint32_t* __restrict__ ctxpk,
                       const int* __restrict__ dlen) {
    extern __shared__ uint32_t smu[];

    const int qt = blockIdx.x;
    const int bh = blockIdx.y;
    const int b  = bh >> 3;
    const int len = dlen[b];
    if (qt * 128 >= len) return;
    const int nk = (len + 63) >> 6;

    const int tid = threadIdx.x;
    const int warp = tid >> 5;
    const int lane = tid & 31;
    const int qid = lane >> 2;
    const int tq  = lane & 3;
    const int m0  = warp * 16;

    const uint32_t* Qg = Qpk + ((size_t)bh * 1024 + qt * 128) * 32;
    const uint32_t* Kg = Kpk + (size_t)bh * 1024 * 32;
    const uint32_t* Vg = Vpk + (size_t)bh * 512 * 64;

    uint32_t* Qs = smu + 2 * FSTG;
    uint32_t smbase = (uint32_t)__cvta_generic_to_shared(smu);
    uint32_t qbase  = smbase + 2 * FSTG * 4;

    // group 1: Q tile
#pragma unroll
    for (int u = 0; u < 4; u++) {
        int f = tid + u * 256;
        int r = f >> 3, c4 = (f & 7) << 2;
        cpa16(qbase + (r * QP + c4) * 4, Qg + (size_t)r * 32 + c4);
    }
    CP_COMMIT();
    // group 2: K/V tile 0
    {
        uint32_t kd = smbase, vd = smbase + KTILE * 4;
#pragma unroll
        for (int u = 0; u < 2; u++) {
            int f = tid + u * 256;
            int rk = f >> 3, ck = (f & 7) << 2;
            cpa16(kd + (rk * KPT + ck) * 4, Kg + (size_t)rk * 32 + ck);
            int rv = f >> 4, cv = (f & 15) << 2;
            cpa16(vd + (rv * VPT + cv) * 4, Vg + (size_t)rv * 64 + cv);
        }
        CP_COMMIT();
    }
    CP_WAIT(1);
    __syncthreads();

    // Q fragments: 4 d-chunks of k16
    unsigned aq[4][4];
#pragma unroll
    for (int s = 0; s < 4; s++) {
        aq[s][0] = Qs[(m0 + qid) * QP + s * 8 + tq];
        aq[s][1] = Qs[(m0 + qid + 8) * QP + s * 8 + tq];
        aq[s][2] = Qs[(m0 + qid) * QP + s * 8 + tq + 4];
        aq[s][3] = Qs[(m0 + qid + 8) * QP + s * 8 + tq + 4];
    }

    float mr0 = -1e30f, mr1 = -1e30f, lr0 = 0.f, lr1 = 0.f;
    float O[8][4];
#pragma unroll
    for (int n = 0; n < 8; n++)
#pragma unroll
        for (int c = 0; c < 4; c++) O[n][c] = 0.f;

    for (int kt = 0; kt < nk; kt++) {
        __syncthreads();
        if (kt + 1 < nk) {
            uint32_t sb = smbase + ((kt + 1) & 1) * FSTG * 4;
            uint32_t kd = sb, vd = sb + KTILE * 4;
            const uint32_t* kg = Kg + (size_t)(kt + 1) * 64 * 32;
            const uint32_t* vg = Vg + (size_t)(kt + 1) * 32 * 64;
#pragma unroll
            for (int u = 0; u < 2; u++) {
                int f = tid + u * 256;
                int rk = f >> 3, ck = (f & 7) << 2;
                cpa16(kd + (rk * KPT + ck) * 4, kg + (size_t)rk * 32 + ck);
                int rv = f >> 4, cv = (f & 15) << 2;
                cpa16(vd + (rv * VPT + cv) * 4, vg + (size_t)rv * 64 + cv);
            }
            CP_COMMIT();
            CP_WAIT(1);
        } else {
            CP_WAIT(0);
        }
        __syncthreads();

        const uint32_t* Ks = smu + (kt & 1) * FSTG;
        const uint32_t* Vs = Ks + KTILE;

        // ---- S = Q @ K^T (Q pre-scaled) ----
        float c[8][4];
#pragma unroll
        for (int n = 0; n < 8; n++)
#pragma unroll
            for (int j = 0; j < 4; j++) c[n][j] = 0.f;

#pragma unroll
        for (int s = 0; s < 4; s++) {
#pragma unroll
            for (int n = 0; n < 8; n++) {
                unsigned b0 = Ks[(n * 8 + qid) * KPT + s * 8 + tq];
                unsigned b1 = Ks[(n * 8 + qid) * KPT + s * 8 + tq + 4];
                MMA_BF16(c[n][0], c[n][1], c[n][2], c[n][3],
                         aq[s][0], aq[s][1], aq[s][2], aq[s][3], b0, b1);
            }
        }

        // ---- mask + online softmax (mask ASSIGNS; stale-K can't leak) ----
        const int cb = kt * 64 + 2 * tq;
        float mx0 = -1e30f, mx1 = -1e30f;
#pragma unroll
        for (int n = 0; n < 8; n++) {
            int c0 = cb + n * 8, c1 = c0 + 1;
            if (c0 >= len) { c[n][0] = -1e30f; c[n][2] = -1e30f; }
            if (c1 >= len) { c[n][1] = -1e30f; c[n][3] = -1e30f; }
            mx0 = fmaxf(mx0, fmaxf(c[n][0], c[n][1]));
            mx1 = fmaxf(mx1, fmaxf(c[n][2], c[n][3]));
        }
        mx0 = fmaxf(mx0, __shfl_xor_sync(0xffffffffu, mx0, 1));
        mx0 = fmaxf(mx0, __shfl_xor_sync(0xffffffffu, mx0, 2));
        mx1 = fmaxf(mx1, __shfl_xor_sync(0xffffffffu, mx1, 1));
        mx1 = fmaxf(mx1, __shfl_xor_sync(0xffffffffu, mx1, 2));

        float mn0 = fmaxf(mr0, mx0), mn1 = fmaxf(mr1, mx1);
        float al0 = __expf(mr0 - mn0), al1 = __expf(mr1 - mn1);
        float rs0 = 0.f, rs1 = 0.f;
#pragma unroll
        for (int n = 0; n < 8; n++) {
            c[n][0] = __expf(c[n][0] - mn0);
            c[n][1] = __expf(c[n][1] - mn0);
            c[n][2] = __expf(c[n][2] - mn1);
            c[n][3] = __expf(c[n][3] - mn1);
            rs0 += c[n][0] + c[n][1];
            rs1 += c[n][2] + c[n][3];
        }
        rs0 += __shfl_xor_sync(0xffffffffu, rs0, 1);
        rs0 += __shfl_xor_sync(0xffffffffu, rs0, 2);
        rs1 += __shfl_xor_sync(0xffffffffu, rs1, 1);
        rs1 += __shfl_xor_sync(0xffffffffu, rs1, 2);
        lr0 = lr0 * al0 + rs0;
        lr1 = lr1 * al1 + rs1;
        mr0 = mn0; mr1 = mn1;
#pragma unroll
        for (int n = 0; n < 8; n++) {
            O[n][0] *= al0; O[n][1] *= al0;
            O[n][2] *= al1; O[n][3] *= al1;
        }

        // ---- O += P @ V, P repacked C-frag -> A-frag entirely in registers ----
#pragma unroll
        for (int s = 0; s < 4; s++) {
            unsigned ap0 = pk2(c[2 * s][0],     c[2 * s][1]);
            unsigned ap1 = pk2(c[2 * s][2],     c[2 * s][3]);
            unsigned ap2 = pk2(c[2 * s + 1][0], c[2 * s + 1][1]);
            unsigned ap3 = pk2(c[2 * s + 1][2], c[2 * s + 1][3]);
#pragma unroll
            for (int n = 0; n < 8; n++) {
                unsigned b0 = Vs[(s * 8 + tq) * VPT + n * 8 + qid];
                unsigned b1 = Vs[(s * 8 + tq + 4) * VPT + n * 8 + qid];
                MMA_BF16(O[n][0], O[n][1], O[n][2], O[n][3],
                         ap0, ap1, ap2, ap3, b0, b1);
            }
        }
    }

    // ---- epilogue: packed ctx ----
    float inv0 = 1.f / lr0, inv1 = 1.f / lr1;
    int h = bh & 7;
    size_t row0 = (size_t)(b * Sn + qt * 128 + m0 + qid);
#pragma unroll
    for (int n = 0; n < 8; n++) {
        int dp = h * 32 + 4 * n + tq;
        ctxpk[row0 * 256 + dp]       = pk2(O[n][0] * inv0, O[n][1] * inv0);
        ctxpk[(row0 + 8) * 256 + dp] = pk2(O[n][2] * inv1, O[n][3] * inv1);
    }
}

// ============================ add + layernorm ===============================
__device__ __forceinline__ float blk_sum_128(float v, float* red) {
#pragma unroll
    for (int o = 16; o; o >>= 1) v += __shfl_xor_sync(0xffffffffu, v, o);
    __syncthreads();
    if ((threadIdx.x & 31) == 0) red[threadIdx.x >> 5] = v;
    __syncthreads();
    return red[0] + red[1] + red[2] + red[3];
}

__global__ __launch_bounds__(128)
void add_ln_kernel(float* __restrict__ x, uint32_t* __restrict__ xpk,
                   const float* __restrict__ hh,
                   const float* __restrict__ g, const float* __restrict__ be,
                   const int* __restrict__ dlen) {
    int row = blockIdx.x;
    if ((row & 1023) >= dlen[row >> 10]) return;
    __shared__ float red[4];
    int t = threadIdx.x;
    size_t off = (size_t)row * 512 + t * 4;
    float4 xv = *(float4*)(x + off);
    float4 hv = *(const float4*)(hh + off);
    float v0 = xv.x + hv.x, v1 = xv.y + hv.y, v2 = xv.z + hv.z, v3 = xv.w + hv.w;
    float mean = blk_sum_128(v0 + v1 + v2 + v3, red) * (1.f / 512.f);
    float d0 = v0 - mean, d1 = v1 - mean, d2 = v2 - mean, d3 = v3 - mean;
    float var = blk_sum_128(d0 * d0 + d1 * d1 + d2 * d2 + d3 * d3, red) * (1.f / 512.f);
    float rstd = rsqrtf(var + 1e-5f);
    float4 gv = *(const float4*)(g + t * 4);
    float4 bv = *(const float4*)(be + t * 4);
    float4 o;
    o.x = d0 * rstd * gv.x + bv.x;
    o.y = d1 * rstd * gv.y + bv.y;
    o.z = d2 * rstd * gv.z + bv.z;
    o.w = d3 * rstd * gv.w + bv.w;
    *(float4*)(x + off) = o;
    uint2 p;
    p.x = pk2(o.x, o.y);
    p.y = pk2(o.z, o.w);
    *(uint2*)(xpk + (size_t)row * 256 + t * 2) = p;
}

// ============================ final head ====================================
#define HEAD_SMEM (512 * 32 * 4)

__global__ __launch_bounds__(256)
void final_logits_kernel(const float* __restrict__ x, const float* __restrict__ addr,
                         const float* __restrict__ poi, const int* __restrict__ atype,
                         const float* __restrict__ Wa, const float* __restrict__ ba,
                         const float* __restrict__ Wout, const float* __restrict__ Wcomb,
                         const int* __restrict__ dlen, float* __restrict__ logits) {
    extern __shared__ float ws[];
    for (int i = threadIdx.x; i < 512 * 32; i += 256) ws[i] = Wout[i];
    __syncthreads();

    const int warp = threadIdx.x >> 5;
    const int lane = threadIdx.x & 31;
    const float wc = Wcomb[lane];

    for (int tok = blockIdx.x * 8 + warp; tok < BSn; tok += gridDim.x * 8) {
        int b = tok >> 10;
        int s = tok & 1023;
        if (s >= dlen[b]) continue;
        int t = atype[b];
        float aj = ba[lane]
                 + addr[b]        * Wa[lane]
                 + poi[t * 3 + 0] * Wa[32 + lane]
                 + poi[t * 3 + 1] * Wa[64 + lane]
                 + poi[t * 3 + 2] * Wa[96 + lane];
        const float* xr = x + (size_t)tok * 512;
        float acc = 0.f;
        for (int d0 = 0; d0 < 512; d0 += 32) {
            float xv = xr[d0 + lane];
#pragma unroll
            for (int j = 0; j < 32; j++)
                acc += __shfl_sync(0xffffffffu, xv, j) * ws[(d0 + j) * 32 + lane];
        }
        float tv = tanhf(acc + aj) * wc;
#pragma unroll
        for (int o = 16; o; o >>= 1) tv += __shfl_xor_sync(0xffffffffu, tv, o);
        if (lane == 0) logits[tok] = tv;
    }
}

__global__ __launch_bounds__(256)
void logsoftmax_kernel(const float* __restrict__ logits, const int* __restrict__ dlen,
                       float* __restrict__ out) {
    __shared__ float red[8];
    int b = blockIdx.x;
    int len = dlen[b];
    const float* lg = logits + (size_t)b * Sn;
    float mx = -1e30f;
    for (int s = threadIdx.x; s < len; s += 256) mx = fmaxf(mx, lg[s]);
#pragma unroll
    for (int o = 16; o; o >>= 1) mx = fmaxf(mx, __shfl_xor_sync(0xffffffffu, mx, o));
    if ((threadIdx.x & 31) == 0) red[threadIdx.x >> 5] = mx;
    __syncthreads();
    mx = red[0];
#pragma unroll
    for (int w = 1; w < 8; w++) mx = fmaxf(mx, red[w]);
    __syncthreads();
    float sum = 0.f;
    for (int s = threadIdx.x; s < len; s += 256) sum += expf(lg[s] - mx);
#pragma unroll
    for (int o = 16; o; o >>= 1) sum += __shfl_xor_sync(0xffffffffu, sum, o);
    if ((threadIdx.x & 31) == 0) red[threadIdx.x >> 5] = sum;
    __syncthreads();
    sum = red[0] + red[1] + red[2] + red[3] + red[4] + red[5] + red[6] + red[7];
    float lse = logf(sum) + mx;
    for (int s = threadIdx.x; s < Sn; s += 256)
        out[(size_t)b * Sn + s] = (s < len) ? (lg[s] - lse) : 0.f;
}

// ============================ launch ========================================
extern "C" void kernel_launch(void* const* d_in, const int* in_sizes, int n_in,
                              void* d_out, int out_size) {
    const float* addr  = (const float*)d_in[0];
    const float* loc   = (const float*)d_in[1];
    const float* tdist = (const float*)d_in[2];
    const float* Wtd   = (const float*)d_in[3];
    const float* btd   = (const float*)d_in[4];
    const float* Wemb  = (const float*)d_in[5];
    const float* bemb  = (const float*)d_in[6];
    const float* Wqkv  = (const float*)d_in[7];
    const float* bqkv  = (const float*)d_in[8];
    const float* Wo    = (const float*)d_in[9];
    const float* bo    = (const float*)d_in[10];
    const float* ln1g  = (const float*)d_in[11];
    const float* ln1b  = (const float*)d_in[12];
    const float* W1    = (const float*)d_in[13];
    const float* b1    = (const float*)d_in[14];
    const float* W2    = (const float*)d_in[15];
    const float* b2    = (const float*)d_in[16];
    const float* ln2g  = (const float*)d_in[17];
    const float* ln2b  = (const float*)d_in[18];
    const float* poi   = (const float*)d_in[19];
    const float* Wa    = (const float*)d_in[20];
    const float* ba    = (const float*)d_in[21];
    const float* Wout  = (const float*)d_in[22];
    const float* Wcomb = (const float*)d_in[23];
    const int*   atype = (const int*)d_in[24];
    const int*   dlen  = (const int*)d_in[25];
    float* out = (float*)d_out;

    float *x, *t1, *lg;
    uint32_t *xpk, *qpk, *kpk, *vpk, *ctxpk, *t2pk, *wqkv, *wo, *w1, *w2;
    cudaGetSymbolAddress((void**)&x,     g_x);
    cudaGetSymbolAddress((void**)&xpk,   g_xpk);
    cudaGetSymbolAddress((void**)&qpk,   g_qpk);
    cudaGetSymbolAddress((void**)&kpk,   g_kpk);
    cudaGetSymbolAddress((void**)&vpk,   g_vpk);
    cudaGetSymbolAddress((void**)&ctxpk, g_ctxpk);
    cudaGetSymbolAddress((void**)&t1,    g_t1);
    cudaGetSymbolAddress((void**)&t2pk,  g_t2pk);
    cudaGetSymbolAddress((void**)&wqkv,  g_wqkv);
    cudaGetSymbolAddress((void**)&wo,    g_wo);
    cudaGetSymbolAddress((void**)&w1,    g_w1);
    cudaGetSymbolAddress((void**)&w2,    g_w2);
    cudaGetSymbolAddress((void**)&lg,    g_logits);

    cudaFuncSetAttribute(flash_bf16_kernel,
                         cudaFuncAttributeMaxDynamicSharedMemorySize, FLASH_SMEM);
    cudaFuncSetAttribute(final_logits_kernel,
                         cudaFuncAttributeMaxDynamicSharedMemorySize, HEAD_SMEM);

    // pack all weights (bf16x2 along K)
    pack_w_kernel<<<(Ln * 256 * 1536 + 255) / 256, 256>>>(Wqkv, wqkv, Ln * 256, 1536);
    pack_w_kernel<<<(Ln * 256 * 512 + 255) / 256, 256>>>(Wo, wo, Ln * 256, 512);
    pack_w_kernel<<<(Ln * 256 * 512 + 255) / 256, 256>>>(W1, w1, Ln * 256, 512);
    pack_w_kernel<<<(Ln * 256 * 512 + 255) / 256, 256>>>(W2, w2, Ln * 256, 512);

    embed_kernel<<<BSn, 128>>>(loc, tdist, Wtd, btd, Wemb, bemb, x, xpk);

    for (int l = 0; l < Ln; l++) {
        bf16_gemm<2><<<dim3(12, 256), 256>>>(
            xpk, wqkv + (size_t)l * 256 * 1536, bqkv + l * 1536,
            nullptr, nullptr, qpk, kpk, vpk, dlen, BSn, 1536, 256);
        flash_bf16_kernel<<<dim3(8, Bn * Hn), 256, FLASH_SMEM>>>(qpk, kpk, vpk,
                                                                 ctxpk, dlen);
        bf16_gemm<0><<<dim3(4, 256), 256>>>(
            ctxpk, wo + (size_t)l * 256 * 512, bo + l * 512,
            t1, nullptr, nullptr, nullptr, nullptr, dlen, BSn, 512, 256);
        add_ln_kernel<<<BSn, 128>>>(x, xpk, t1, ln1g + l * 512, ln1b + l * 512, dlen);
        bf16_gemm<1><<<dim3(4, 256), 256>>>(
            xpk, w1 + (size_t)l * 256 * 512, b1 + l * 512,
            nullptr, t2pk, nullptr, nullptr, nullptr, dlen, BSn, 512, 256);
        bf16_gemm<0><<<dim3(4, 256), 256>>>(
            t2pk, w2 + (size_t)l * 256 * 512, b2 + l * 512,
            t1, nullptr, nullptr, nullptr, nullptr, dlen, BSn, 512, 256);
        add_ln_kernel<<<BSn, 128>>>(x, xpk, t1, ln2g + l * 512, ln2b + l * 512, dlen);
    }

    final_logits_kernel<<<512, 256, HEAD_SMEM>>>(x, addr, poi, atype, Wa, ba,
                                                 Wout, Wcomb, dlen, lg);
    logsoftmax_kernel<<<Bn, 256>>>(lg, dlen, out);
}